// round 14
// baseline (speedup 1.0000x reference)
#include <cuda_runtime.h>
#include <cuda_fp16.h>
#include <cstdint>
#include <math.h>

#define NROWS 8192
#define D     512
#define CB    4096
#define FB    8192
#define BM    128
#define BN    128
#define KC    32
#define NCH   (D / KC)
#define THRESH 4e-3f
#define SMEM_DYN 98304
// vq_gemm shape
#define VBN   256
#define VKC   64
#define VNCH  (D / VKC)
#define VSTAGE 49152u
#define VSMEM (3 * 49152)
#define MAXTILES 32

typedef unsigned long long ull;

// -------------------- device scratch --------------------
__device__ float g_nsq_c[CB], g_nsq_f[FB];
__device__ float g_xnsq_c[NROWS], g_xnsq_f[NROWS];
__device__ ull   g_b1c[NROWS], g_b2c[NROWS], g_b1f[NROWS], g_b2f[NROWS];
__device__ ull   g_ex[NROWS];
__device__ ull   g_tmin[NROWS * MAXTILES];
__device__ int   g_idx_c[NROWS], g_idx_f[NROWS];
__device__ int   g_list[NROWS];
__device__ int   g_cnt_c, g_cnt_f;
__device__ float g_qc[NROWS * D], g_qf[NROWS * D];
__device__ float g_ci[NROWS * D], g_res[NROWS * D], g_h[NROWS * D];
__device__ __half g_zc_h[NROWS * D], g_zc_l[NROWS * D];
__device__ __half g_ce_h[CB * D],   g_ce_l[CB * D];
__device__ __half g_fe_h[FB * D],   g_fe_l[FB * D];
__device__ __half g_res_h[NROWS * D], g_res_l[NROWS * D];
__device__ __half g_q_h[NROWS * D],   g_q_l[NROWS * D];
__device__ __half g_w1_h[D * D], g_w1_l[D * D], g_w2_h[D * D], g_w2_l[D * D];
__device__ float g_loss;

// -------------------- helpers --------------------
__device__ __forceinline__ uint32_t smem_u32(const void* p) {
    uint32_t a;
    asm("{ .reg .u64 t; cvta.to.shared.u64 t, %1; cvt.u32.u64 %0, t; }" : "=r"(a) : "l"(p));
    return a;
}
#define SWZ32(o)  ((o) ^ (((o) >> 3) & 0x30))   // 64B rows
#define SWZ128(o) ((o) ^ (((o) >> 3) & 0x70))   // 128B rows
#define LDM4(r0, r1, r2, r3, a) \
    asm volatile("ldmatrix.sync.aligned.m8n8.x4.shared.b16 {%0,%1,%2,%3}, [%4];" \
        : "=r"(r0), "=r"(r1), "=r"(r2), "=r"(r3) : "r"(a))
#define MMA_F16(c, a, b) \
    asm volatile("mma.sync.aligned.m16n8k16.row.col.f32.f16.f16.f32 " \
        "{%0,%1,%2,%3}, {%4,%5,%6,%7}, {%8,%9}, {%0,%1,%2,%3};" \
        : "+f"((c)[0]), "+f"((c)[1]), "+f"((c)[2]), "+f"((c)[3]) \
        : "r"((a)[0]), "r"((a)[1]), "r"((a)[2]), "r"((a)[3]), "r"((b)[0]), "r"((b)[1]))
#define CP_ASYNC16(dst, src) \
    asm volatile("cp.async.cg.shared.global [%0], [%1], 16;" :: "r"(dst), "l"(src))
#define CP_COMMIT() asm volatile("cp.async.commit_group;")
#define CP_WAIT1()  asm volatile("cp.async.wait_group 1;")

__device__ __forceinline__ ull packdi(float d, unsigned j) {
    unsigned u = __float_as_uint(d);
    u = (u & 0x80000000u) ? ~u : (u | 0x80000000u);
    return ((ull)u << 32) | (ull)j;
}
__device__ __forceinline__ float unpackd(ull p) {
    unsigned u = (unsigned)(p >> 32);
    u = (u & 0x80000000u) ? (u & 0x7fffffffu) : ~u;
    return __uint_as_float(u);
}
__device__ __forceinline__ void top2ins(ull& m1, ull& m2, ull p) {
    if (p < m1) { m2 = m1; m1 = p; }
    else if (p < m2) m2 = p;
}

// -------------------- launch 1: init --------------------
__global__ void init_kernel() {
    int r = blockIdx.x * blockDim.x + threadIdx.x;
    if (r < NROWS) {
        g_b1c[r] = ~0ull; g_b2c[r] = ~0ull;
        g_b1f[r] = ~0ull; g_b2f[r] = ~0ull;
    }
}
// -------------------- launch 2: zero scalars --------------------
__global__ void zero_kernel() {
    if (threadIdx.x == 0) { g_loss = 0.f; g_cnt_c = 0; g_cnt_f = 0; }
}

// -------------------- launch 3: fused norms + fp16 hi/lo splits --------------------
__global__ void prep_split(const float* __restrict__ z,
                           const float* __restrict__ ce, const float* __restrict__ fe,
                           const float* __restrict__ w1, const float* __restrict__ w2) {
    int gw = (blockIdx.x * blockDim.x + threadIdx.x) >> 5;
    int lane = threadIdx.x & 31;
    const float* src;
    __half *hi, *lo;
    float* nrm = nullptr;
    if (gw < CB) {
        src = ce + (size_t)gw * D; hi = g_ce_h + (size_t)gw * D; lo = g_ce_l + (size_t)gw * D;
        nrm = g_nsq_c + gw;
    } else if (gw < CB + FB) {
        int r = gw - CB;
        src = fe + (size_t)r * D; hi = g_fe_h + (size_t)r * D; lo = g_fe_l + (size_t)r * D;
        nrm = g_nsq_f + r;
    } else if (gw < CB + FB + NROWS) {
        int r = gw - CB - FB;
        src = z + (size_t)r * 1024; hi = g_zc_h + (size_t)r * D; lo = g_zc_l + (size_t)r * D;
        nrm = g_xnsq_c + r;
    } else if (gw < CB + FB + NROWS + D) {
        int r = gw - CB - FB - NROWS;
        src = w1 + (size_t)r * D; hi = g_w1_h + (size_t)r * D; lo = g_w1_l + (size_t)r * D;
    } else if (gw < CB + FB + NROWS + 2 * D) {
        int r = gw - CB - FB - NROWS - D;
        src = w2 + (size_t)r * D; hi = g_w2_h + (size_t)r * D; lo = g_w2_l + (size_t)r * D;
    } else return;

    float s = 0.f;
    #pragma unroll
    for (int it = 0; it < 4; it++) {
        int c = lane * 4 + it * 128;
        float4 v = *(const float4*)(src + c);
        s += v.x * v.x + v.y * v.y + v.z * v.z + v.w * v.w;
        __half hs[4], ls[4];
        hs[0] = __float2half_rn(v.x); ls[0] = __float2half_rn(v.x - __half2float(hs[0]));
        hs[1] = __float2half_rn(v.y); ls[1] = __float2half_rn(v.y - __half2float(hs[1]));
        hs[2] = __float2half_rn(v.z); ls[2] = __float2half_rn(v.z - __half2float(hs[2]));
        hs[3] = __float2half_rn(v.w); ls[3] = __float2half_rn(v.w - __half2float(hs[3]));
        *(uint2*)(hi + c) = *(uint2*)hs;
        *(uint2*)(lo + c) = *(uint2*)ls;
    }
    if (nrm) {
        #pragma unroll
        for (int o = 16; o; o >>= 1) s += __shfl_xor_sync(0xffffffffu, s, o);
        if (lane == 0) *nrm = s;
    }
}

// -------------------- VQ GEMM: 512 threads, 128x256 tile, KC=64, single-pass hh --------------------
__global__ __launch_bounds__(512, 1) void vq_gemm(
    const __half* __restrict__ Ah, const __half* __restrict__ Bh,
    const float* __restrict__ aux, const float* __restrict__ xnsq,
    ull* __restrict__ best1, ull* __restrict__ best2,
    ull* __restrict__ tilemin)
{
    extern __shared__ char sm[];
    __shared__ ull sb1[BM], sb2[BM];
    const int t = threadIdx.x;
    const int lane = t & 31, wid = t >> 5;
    const int warp_m = wid & 1, warp_n = wid >> 1;   // 2 x 8 warp grid, 64x32 tiles
    const int row0 = blockIdx.x * BM, col0 = blockIdx.y * VBN;
    const uint32_t smb = smem_u32(sm);

    if (t < BM) { sb1[t] = ~0ull; sb2[t] = ~0ull; }

    float acc[4][4][4];
    #pragma unroll
    for (int i = 0; i < 4; i++)
        #pragma unroll
        for (int j = 0; j < 4; j++)
            #pragma unroll
            for (int k = 0; k < 4; k++) acc[i][j][k] = 0.f;

    // A: 128 rows x 128B (KC=64); thread t -> row t>>2, 32B seg (t&3); 2 x 16B CPs
    const int ar = t >> 2, as = t & 3;
    const size_t aoff = (size_t)(row0 + ar) * D + as * 16;
    const uint32_t sa0 = SWZ128((uint32_t)(ar * 128 + as * 32));
    const uint32_t sa1 = SWZ128((uint32_t)(ar * 128 + as * 32 + 16));
    // B: 256 rows x 128B; thread t -> row t>>1, 64B seg (t&1); 4 x 16B CPs
    const int br = t >> 1, bs = t & 1;
    const size_t boff = (size_t)(col0 + br) * D + bs * 32;
    const uint32_t sb0 = SWZ128((uint32_t)(br * 128 + bs * 64));
    const uint32_t sb1o = SWZ128((uint32_t)(br * 128 + bs * 64 + 16));
    const uint32_t sb2o = SWZ128((uint32_t)(br * 128 + bs * 64 + 32));
    const uint32_t sb3o = SWZ128((uint32_t)(br * 128 + bs * 64 + 48));

    // stage: A +0 (16K), B +16384 (32K); stride 49152
    #define VISSUE(c) do { \
        uint32_t bb = smb + (uint32_t)((c) % 3) * VSTAGE; \
        const int kb = (c) * VKC; \
        CP_ASYNC16(bb + sa0, (const char*)(Ah + aoff + kb)); \
        CP_ASYNC16(bb + sa1, (const char*)(Ah + aoff + kb + 8)); \
        CP_ASYNC16(bb + 16384u + sb0,  (const char*)(Bh + boff + kb)); \
        CP_ASYNC16(bb + 16384u + sb1o, (const char*)(Bh + boff + kb + 8)); \
        CP_ASYNC16(bb + 16384u + sb2o, (const char*)(Bh + boff + kb + 16)); \
        CP_ASYNC16(bb + 16384u + sb3o, (const char*)(Bh + boff + kb + 24)); \
        CP_COMMIT(); \
    } while (0)

    VISSUE(0);
    VISSUE(1);

    #pragma unroll 1
    for (int c = 0; c < VNCH; c++) {
        const uint32_t bb = smb + (uint32_t)(c % 3) * VSTAGE;
        CP_WAIT1();
        __syncthreads();
        if (c + 2 < VNCH) VISSUE(c + 2);
        #pragma unroll
        for (int k16 = 0; k16 < 4; k16++) {
            uint32_t bhf[4][2], ah[4][4];
            #pragma unroll
            for (int nt2 = 0; nt2 < 2; nt2++) {
                int nrow = warp_n * 32 + nt2 * 16 + (lane & 7) + ((lane & 16) ? 8 : 0);
                int kbyte = k16 * 32 + ((lane >> 3) & 1) * 16;
                uint32_t off = SWZ128((uint32_t)(nrow * 128 + kbyte));
                LDM4(bhf[nt2 * 2][0], bhf[nt2 * 2][1], bhf[nt2 * 2 + 1][0], bhf[nt2 * 2 + 1][1],
                     bb + 16384u + off);
            }
            #pragma unroll
            for (int mt = 0; mt < 4; mt++) {
                int mrow = warp_m * 64 + mt * 16 + (lane & 15);
                int kbyte = k16 * 32 + (lane >> 4) * 16;
                uint32_t off = SWZ128((uint32_t)(mrow * 128 + kbyte));
                LDM4(ah[mt][0], ah[mt][1], ah[mt][2], ah[mt][3], bb + off);
            }
            #pragma unroll
            for (int mt = 0; mt < 4; mt++)
                #pragma unroll
                for (int nt = 0; nt < 4; nt++) MMA_F16(acc[mt][nt], ah[mt], bhf[nt]);
        }
    }

    const int g = lane >> 2, tg = lane & 3;
    #pragma unroll
    for (int mt = 0; mt < 4; mt++) {
        #pragma unroll
        for (int h8 = 0; h8 < 2; h8++) {
            int lrow2 = warp_m * 64 + mt * 16 + g + h8 * 8;
            float xx = xnsq[row0 + lrow2];
            ull m1 = ~0ull, m2 = ~0ull;
            #pragma unroll
            for (int nt = 0; nt < 4; nt++) {
                int colg = col0 + warp_n * 32 + nt * 8 + tg * 2;
                float d0 = __fadd_rn(__fadd_rn(xx, aux[colg]), -2.f * acc[mt][nt][h8 * 2 + 0]);
                float d1 = __fadd_rn(__fadd_rn(xx, aux[colg + 1]), -2.f * acc[mt][nt][h8 * 2 + 1]);
                top2ins(m1, m2, packdi(d0, (unsigned)colg));
                top2ins(m1, m2, packdi(d1, (unsigned)(colg + 1)));
            }
            #pragma unroll
            for (int o = 1; o <= 2; o <<= 1) {
                ull o1 = __shfl_xor_sync(0xffffffffu, m1, o);
                ull o2 = __shfl_xor_sync(0xffffffffu, m2, o);
                ull n1 = o1 < m1 ? o1 : m1;
                ull hi = o1 > m1 ? o1 : m1;
                ull lo2 = o2 < m2 ? o2 : m2;
                m2 = hi < lo2 ? hi : lo2;
                m1 = n1;
            }
            if (tg == 0) {
                ull old = atomicMin(&sb1[lrow2], m1);
                atomicMin(&sb2[lrow2], old > m1 ? old : m1);
                atomicMin(&sb2[lrow2], m2);
            }
        }
    }
    __syncthreads();
    if (t < BM) {
        ull s1 = sb1[t], s2 = sb2[t];
        ull old = atomicMin(&best1[row0 + t], s1);
        atomicMin(&best2[row0 + t], old > s1 ? old : s1);
        atomicMin(&best2[row0 + t], s2);
        tilemin[(size_t)(row0 + t) * MAXTILES + blockIdx.y] = s1;
    }
    #undef VISSUE
}

// -------------------- MLP GEMM: 3-pass emulated fp32, 256 threads (R13 shape) --------------------
__global__ __launch_bounds__(256, 2) void mlp_gemm(
    const __half* __restrict__ Ah, const __half* __restrict__ Al,
    const __half* __restrict__ Bh, const __half* __restrict__ Bl,
    const float* __restrict__ aux, float* __restrict__ out)
{
    extern __shared__ char sm[];
    const int t = threadIdx.x;
    const int lane = t & 31, wid = t >> 5;
    const int warp_m = wid & 1, warp_n = wid >> 1;
    const int row0 = blockIdx.x * BM, col0 = blockIdx.y * BN;
    const uint32_t smb = smem_u32(sm);

    float acc[4][4][4];
    #pragma unroll
    for (int i = 0; i < 4; i++)
        #pragma unroll
        for (int j = 0; j < 4; j++)
            #pragma unroll
            for (int k = 0; k < 4; k++) acc[i][j][k] = 0.f;

    const int lrow = t >> 1, lh = t & 1;
    const size_t aoff = (size_t)(row0 + lrow) * D + lh * 16;
    const size_t boff = (size_t)(col0 + lrow) * D + lh * 16;
    const uint32_t st0 = SWZ32((uint32_t)(lrow * 64 + lh * 32));
    const uint32_t st1 = SWZ32((uint32_t)(lrow * 64 + lh * 32 + 16));

    #define MISSUE(c) do { \
        uint32_t bb = smb + (uint32_t)((c) % 3) * 32768u; \
        const int kb = (c) * KC; \
        CP_ASYNC16(bb + st0, (const char*)(Ah + aoff + kb)); \
        CP_ASYNC16(bb + st1, (const char*)(Ah + aoff + kb + 8)); \
        CP_ASYNC16(bb + 8192u  + st0, (const char*)(Al + aoff + kb)); \
        CP_ASYNC16(bb + 8192u  + st1, (const char*)(Al + aoff + kb + 8)); \
        CP_ASYNC16(bb + 16384u + st0, (const char*)(Bh + boff + kb)); \
        CP_ASYNC16(bb + 16384u + st1, (const char*)(Bh + boff + kb + 8)); \
        CP_ASYNC16(bb + 24576u + st0, (const char*)(Bl + boff + kb)); \
        CP_ASYNC16(bb + 24576u + st1, (const char*)(Bl + boff + kb + 8)); \
        CP_COMMIT(); \
    } while (0)

    MISSUE(0);
    MISSUE(1);

    #pragma unroll 1
    for (int c = 0; c < NCH; c++) {
        const uint32_t bb = smb + (uint32_t)(c % 3) * 32768u;
        CP_WAIT1();
        __syncthreads();
        if (c + 2 < NCH) MISSUE(c + 2);
        #pragma unroll
        for (int k16 = 0; k16 < 2; k16++) {
            uint32_t bhf[4][2], blf[4][2], ah[4][4], al[4][4];
            #pragma unroll
            for (int nt2 = 0; nt2 < 2; nt2++) {
                int nrow = warp_n * 32 + nt2 * 16 + (lane & 7) + ((lane & 16) ? 8 : 0);
                int kbyte = k16 * 32 + ((lane >> 3) & 1) * 16;
                uint32_t off = SWZ32((uint32_t)(nrow * 64 + kbyte));
                LDM4(bhf[nt2 * 2][0], bhf[nt2 * 2][1], bhf[nt2 * 2 + 1][0], bhf[nt2 * 2 + 1][1], bb + 16384u + off);
            }
            #pragma unroll
            for (int mt = 0; mt < 4; mt++) {
                int mrow = warp_m * 64 + mt * 16 + (lane & 15);
                int kbyte = k16 * 32 + (lane >> 4) * 16;
                uint32_t off = SWZ32((uint32_t)(mrow * 64 + kbyte));
                LDM4(ah[mt][0], ah[mt][1], ah[mt][2], ah[mt][3], bb + off);
            }
            #pragma unroll
            for (int nt2 = 0; nt2 < 2; nt2++) {
                int nrow = warp_n * 32 + nt2 * 16 + (lane & 7) + ((lane & 16) ? 8 : 0);
                int kbyte = k16 * 32 + ((lane >> 3) & 1) * 16;
                uint32_t off = SWZ32((uint32_t)(nrow * 64 + kbyte));
                LDM4(blf[nt2 * 2][0], blf[nt2 * 2][1], blf[nt2 * 2 + 1][0], blf[nt2 * 2 + 1][1], bb + 24576u + off);
            }
            #pragma unroll
            for (int mt = 0; mt < 4; mt++)
                #pragma unroll
                for (int nt = 0; nt < 4; nt++) MMA_F16(acc[mt][nt], ah[mt], bhf[nt]);
            #pragma unroll
            for (int mt = 0; mt < 4; mt++) {
                int mrow = warp_m * 64 + mt * 16 + (lane & 15);
                int kbyte = k16 * 32 + (lane >> 4) * 16;
                uint32_t off = SWZ32((uint32_t)(mrow * 64 + kbyte));
                LDM4(al[mt][0], al[mt][1], al[mt][2], al[mt][3], bb + 8192u + off);
            }
            #pragma unroll
            for (int mt = 0; mt < 4; mt++)
                #pragma unroll
                for (int nt = 0; nt < 4; nt++) MMA_F16(acc[mt][nt], ah[mt], blf[nt]);
            #pragma unroll
            for (int mt = 0; mt < 4; mt++)
                #pragma unroll
                for (int nt = 0; nt < 4; nt++) MMA_F16(acc[mt][nt], al[mt], bhf[nt]);
        }
    }

    const int g = lane >> 2, tg = lane & 3;
    #pragma unroll
    for (int mt = 0; mt < 4; mt++) {
        #pragma unroll
        for (int h8 = 0; h8 < 2; h8++) {
            int row = row0 + warp_m * 64 + mt * 16 + g + h8 * 8;
            #pragma unroll
            for (int nt = 0; nt < 4; nt++) {
                int colg = col0 + warp_n * 32 + nt * 8 + tg * 2;
                float2 o2 = make_float2(acc[mt][nt][h8 * 2 + 0] + aux[colg],
                                        acc[mt][nt][h8 * 2 + 1] + aux[colg + 1]);
                *(float2*)&out[(size_t)row * D + colg] = o2;
            }
        }
    }
    #undef MISSUE
}

// -------------------- flag: compact near-tie rows --------------------
__global__ void flag_kernel(const ull* __restrict__ b1, const ull* __restrict__ b2,
                            int* __restrict__ idx, int* __restrict__ list, int* __restrict__ cnt) {
    int r = blockIdx.x * blockDim.x + threadIdx.x;
    if (r >= NROWS) return;
    ull p1 = b1[r];
    idx[r] = (int)(p1 & 0xffffffffu);
    g_ex[r] = ~0ull;
    if (unpackd(b2[r]) - unpackd(p1) <= THRESH) {
        int pos = atomicAdd(cnt, 1);
        list[pos] = r;
    }
}

// -------------------- exact re-decide, tile-pruned (256-wide tiles) --------------------
__global__ void exact_kernel(const float* __restrict__ x, int ldx,
                             const float* __restrict__ emb, int ntiles,
                             const float* __restrict__ nsq, const float* __restrict__ xnsq,
                             const int* __restrict__ list, const int* __restrict__ cnt,
                             const ull* __restrict__ b1, const ull* __restrict__ tilemin,
                             ull* __restrict__ ex) {
    int i = blockIdx.x;
    if (i >= *cnt) return;
    int r = list[i];
    __shared__ float xs[D];
    __shared__ ull wmin[8];
    const int t = threadIdx.x, lane = t & 31, w = t >> 5;
    if (t < 128) ((float4*)xs)[t] = *(const float4*)(x + (size_t)r * ldx + t * 4);
    if (t < 8) wmin[t] = ~0ull;
    __syncthreads();
    float xx = xnsq[r];
    float dcut = unpackd(b1[r]) + 2.f * THRESH;
    ull m = ~0ull;
    for (int tt = 0; tt < ntiles; tt++) {
        if (unpackd(tilemin[(size_t)r * MAXTILES + tt]) > dcut) continue;
        for (int cc = w; cc < VBN; cc += 8) {
            int j = tt * VBN + cc;
            const float* e = emb + (size_t)j * D;
            float s = 0.f;
            for (int k = lane; k < D; k += 32) s = fmaf(e[k], xs[k], s);
            #pragma unroll
            for (int o = 16; o; o >>= 1) s += __shfl_xor_sync(0xffffffffu, s, o);
            if (lane == 0) {
                float d = __fadd_rn(__fadd_rn(xx, nsq[j]), -2.f * s);
                ull p = packdi(d, (unsigned)j);
                if (p < m) m = p;
            }
        }
    }
    if (lane == 0) wmin[w] = m;
    __syncthreads();
    if (t == 0) {
        ull mm = wmin[0];
        #pragma unroll
        for (int k = 1; k < 8; k++) if (wmin[k] < mm) mm = wmin[k];
        ex[r] = mm;
    }
}

// -------------------- select exact winners --------------------
__global__ void sel_kernel(const int* __restrict__ list, const int* __restrict__ cnt,
                           const ull* __restrict__ ex, int* __restrict__ idx) {
    int i = blockIdx.x * blockDim.x + threadIdx.x;
    if (i < *cnt) { int r = list[i]; idx[r] = (int)(ex[r] & 0xffffffffu); }
}

// -------------------- gather q = emb[idx] (+ split), loss --------------------
__global__ void gather_loss(const float* __restrict__ emb, const int* __restrict__ idx,
                            const float* __restrict__ x, int ldx, float* __restrict__ q,
                            __half* __restrict__ qh, __half* __restrict__ ql) {
    int r = blockIdx.x;
    int j = idx[r];
    const float* e = emb + (size_t)j * D;
    const float* xr = x + (size_t)r * ldx;
    float* qr = q + (size_t)r * D;
    float ls = 0.f;
    for (int k = threadIdx.x; k < D; k += blockDim.x) {
        float ev = e[k];
        qr[k] = ev;
        __half hh = __float2half_rn(ev);
        qh[(size_t)r * D + k] = hh;
        ql[(size_t)r * D + k] = __float2half_rn(ev - __half2float(hh));
        float dd = ev - xr[k];
        ls += dd * dd;
    }
    #pragma unroll
    for (int o = 16; o; o >>= 1) ls += __shfl_xor_sync(0xffffffffu, ls, o);
    __shared__ float ws[8];
    int w = threadIdx.x >> 5;
    if ((threadIdx.x & 31) == 0) ws[w] = ls;
    __syncthreads();
    if (threadIdx.x == 0) {
        float s = 0.f;
        for (int i = 0; i < 8; i++) s += ws[i];
        atomicAdd(&g_loss, s);
    }
}

// -------------------- LayerNorm + leakyReLU + fused follow-up --------------------
template <int MODE>
__global__ void ln_kernel(const float* __restrict__ h,
                          const float* __restrict__ g, const float* __restrict__ be,
                          const float* __restrict__ z,
                          const float* __restrict__ gc_raw, const float* __restrict__ gf_raw,
                          float* __restrict__ out)
{
    int r = blockIdx.x;
    int j = threadIdx.x;
    float hv = h[(size_t)r * D + j];
    float s = hv, sq = hv * hv;
    #pragma unroll
    for (int o = 16; o; o >>= 1) {
        s += __shfl_xor_sync(0xffffffffu, s, o);
        sq += __shfl_xor_sync(0xffffffffu, sq, o);
    }
    __shared__ float s1[16], s2[16];
    int w = j >> 5, lane = j & 31;
    if (lane == 0) { s1[w] = s; s2[w] = sq; }
    __syncthreads();
    if (w == 0) {
        s = (lane < 16) ? s1[lane] : 0.f;
        sq = (lane < 16) ? s2[lane] : 0.f;
        #pragma unroll
        for (int o = 8; o; o >>= 1) {
            s += __shfl_xor_sync(0xffffffffu, s, o);
            sq += __shfl_xor_sync(0xffffffffu, sq, o);
        }
        if (lane == 0) { s1[0] = s; s2[0] = sq; }
    }
    __syncthreads();
    float mean = s1[0] * (1.f / D);
    float var = s2[0] * (1.f / D) - mean * mean;
    float y = (hv - mean) * rsqrtf(var + 1e-5f) * g[j] + be[j];
    float act = y > 0.f ? y : 0.1f * y;
    float gcv = 1.f / (1.f + expf(-gc_raw[0]));

    if (MODE == 0) {
        float rv = z[(size_t)r * 1024 + D + j] - gcv * act;
        g_ci[(size_t)r * D + j] = act;
        g_res[(size_t)r * D + j] = rv;
        __half hh = __float2half_rn(rv);
        g_res_h[(size_t)r * D + j] = hh;
        g_res_l[(size_t)r * D + j] = __float2half_rn(rv - __half2float(hh));
        float rq = rv * rv;
        #pragma unroll
        for (int o = 16; o; o >>= 1) rq += __shfl_xor_sync(0xffffffffu, rq, o);
        __syncthreads();
        if (lane == 0) s1[w] = rq;
        __syncthreads();
        if (j == 0) {
            float tt = 0.f;
            #pragma unroll
            for (int i = 0; i < 16; i++) tt += s1[i];
            g_xnsq_f[r] = tt;
        }
    } else {
        float gfv = 1.f / (1.f + expf(-gf_raw[0]));
        out[(size_t)r * 1024 + j] = g_qc[(size_t)r * D + j] + 0.1f * gfv * act;
        out[(size_t)r * 1024 + D + j] = g_qf[(size_t)r * D + j] + gcv * g_ci[(size_t)r * D + j];
        if (r == 0 && j == 0)
            out[(size_t)NROWS * 1024] = 1.25f * g_loss / (float)((size_t)NROWS * D);
    }
}

// -------------------- launch --------------------
#define SYMADDR(p, s) cudaGetSymbolAddress((void**)&p, s)

extern "C" void kernel_launch(void* const* d_in, const int* in_sizes, int n_in,
                              void* d_out, int out_size) {
    const float* z      = (const float*)d_in[0];
    const float* ce     = (const float*)d_in[1];
    const float* fe     = (const float*)d_in[2];
    const float* w_c2f  = (const float*)d_in[3];
    const float* b_c2f  = (const float*)d_in[4];
    const float* g_c2f  = (const float*)d_in[5];
    const float* be_c2f = (const float*)d_in[6];
    const float* w_f2c  = (const float*)d_in[7];
    const float* b_f2c  = (const float*)d_in[8];
    const float* g_f2c  = (const float*)d_in[9];
    const float* be_f2c = (const float*)d_in[10];
    const float* gc_raw = (const float*)d_in[11];
    const float* gf_raw = (const float*)d_in[12];
    float* out = (float*)d_out;

    float *nsq_c, *nsq_f, *xnsq_c, *xnsq_f, *qc, *qf, *res, *h;
    ull *b1c, *b2c, *b1f, *b2f, *ex, *tmin;
    int *idx_c, *idx_f, *list, *cnt_c, *cnt_f;
    __half *zc_h, *ce_h, *fe_h, *res_h, *q_h, *q_l;
    __half *w1_h, *w1_l, *w2_h, *w2_l;
    SYMADDR(nsq_c, g_nsq_c);   SYMADDR(nsq_f, g_nsq_f);
    SYMADDR(xnsq_c, g_xnsq_c); SYMADDR(xnsq_f, g_xnsq_f);
    SYMADDR(b1c, g_b1c); SYMADDR(b2c, g_b2c); SYMADDR(b1f, g_b1f); SYMADDR(b2f, g_b2f);
    SYMADDR(ex, g_ex); SYMADDR(tmin, g_tmin);
    SYMADDR(idx_c, g_idx_c); SYMADDR(idx_f, g_idx_f);
    SYMADDR(list, g_list);
    SYMADDR(cnt_c, g_cnt_c); SYMADDR(cnt_f, g_cnt_f);
    SYMADDR(qc, g_qc); SYMADDR(qf, g_qf); SYMADDR(res, g_res); SYMADDR(h, g_h);
    SYMADDR(zc_h, g_zc_h);
    SYMADDR(ce_h, g_ce_h);
    SYMADDR(fe_h, g_fe_h);
    SYMADDR(res_h, g_res_h);
    SYMADDR(q_h, g_q_h); SYMADDR(q_l, g_q_l);
    SYMADDR(w1_h, g_w1_h); SYMADDR(w1_l, g_w1_l);
    SYMADDR(w2_h, g_w2_h); SYMADDR(w2_l, g_w2_l);
    __half *zc_l, *ce_l, *fe_l, *res_l;
    SYMADDR(zc_l, g_zc_l); SYMADDR(ce_l, g_ce_l); SYMADDR(fe_l, g_fe_l); SYMADDR(res_l, g_res_l);

    cudaFuncSetAttribute(vq_gemm, cudaFuncAttributeMaxDynamicSharedMemorySize, VSMEM);
    cudaFuncSetAttribute(mlp_gemm, cudaFuncAttributeMaxDynamicSharedMemorySize, SMEM_DYN);

    init_kernel<<<NROWS / 256, 256>>>();
    zero_kernel<<<1, 32>>>();
    {
        int warps = CB + FB + NROWS + 2 * D;
        prep_split<<<(warps * 32 + 255) / 256, 256>>>(z, ce, fe, w_c2f, w_f2c);
    }
    // coarse VQ  (launch #4 — profiled)
    vq_gemm<<<dim3(NROWS / BM, CB / VBN), 512, VSMEM>>>(zc_h, ce_h, nsq_c, xnsq_c, b1c, b2c, tmin);
    flag_kernel<<<NROWS / 256, 256>>>(b1c, b2c, idx_c, list, cnt_c);
    exact_kernel<<<NROWS, 256>>>(z, 1024, ce, CB / VBN, nsq_c, xnsq_c, list, cnt_c, b1c, tmin, ex);
    sel_kernel<<<NROWS / 256, 256>>>(list, cnt_c, ex, idx_c);
    gather_loss<<<NROWS, 256>>>(ce, idx_c, z, 1024, qc, q_h, q_l);
    // MLP c2f
    mlp_gemm<<<dim3(NROWS / BM, D / BN), 256, SMEM_DYN>>>(q_h, q_l, w1_h, w1_l, b_c2f, h);
    ln_kernel<0><<<NROWS, 512>>>(h, g_c2f, be_c2f, z, gc_raw, gf_raw, nullptr);
    // fine VQ
    vq_gemm<<<dim3(NROWS / BM, FB / VBN), 512, VSMEM>>>(res_h, fe_h, nsq_f, xnsq_f, b1f, b2f, tmin);
    flag_kernel<<<NROWS / 256, 256>>>(b1f, b2f, idx_f, list, cnt_f);
    exact_kernel<<<NROWS, 256>>>(res, D, fe, FB / VBN, nsq_f, xnsq_f, list, cnt_f, b1f, tmin, ex);
    sel_kernel<<<NROWS / 256, 256>>>(list, cnt_f, ex, idx_f);
    gather_loss<<<NROWS, 256>>>(fe, idx_f, res, D, qf, q_h, q_l);
    // MLP f2c
    mlp_gemm<<<dim3(NROWS / BM, D / BN), 256, SMEM_DYN>>>(q_h, q_l, w2_h, w2_l, b_f2c, h);
    ln_kernel<1><<<NROWS, 512>>>(h, g_f2c, be_f2c, z, gc_raw, gf_raw, out);
}

// round 15
// speedup vs baseline: 1.1791x; 1.1791x over previous
#include <cuda_runtime.h>
#include <cuda_fp16.h>
#include <cstdint>
#include <math.h>

#define NROWS 8192
#define D     512
#define CB    4096
#define FB    8192
#define BM    128
#define BN    128
#define KC    32
#define NCH   (D / KC)
#define VKC   64
#define VNCH  (D / VKC)
#define THRESH 4e-3f
#define SMEM_DYN 98304
#define MAXTILES 64

typedef unsigned long long ull;

// -------------------- device scratch --------------------
__device__ float g_nsq_c[CB], g_nsq_f[FB];
__device__ float g_xnsq_c[NROWS], g_xnsq_f[NROWS];
__device__ ull   g_b1c[NROWS], g_b2c[NROWS], g_b1f[NROWS], g_b2f[NROWS];
__device__ ull   g_ex[NROWS];
__device__ ull   g_tmin[NROWS * MAXTILES];
__device__ int   g_idx_c[NROWS], g_idx_f[NROWS];
__device__ int   g_list[NROWS];
__device__ int   g_cnt_c, g_cnt_f;
__device__ float g_qc[NROWS * D], g_qf[NROWS * D];
__device__ float g_ci[NROWS * D], g_res[NROWS * D], g_h[NROWS * D];
__device__ __half g_zc_h[NROWS * D], g_zc_l[NROWS * D];
__device__ __half g_ce_h[CB * D],   g_ce_l[CB * D];
__device__ __half g_fe_h[FB * D],   g_fe_l[FB * D];
__device__ __half g_res_h[NROWS * D], g_res_l[NROWS * D];
__device__ __half g_q_h[NROWS * D],   g_q_l[NROWS * D];
__device__ __half g_w1_h[D * D], g_w1_l[D * D], g_w2_h[D * D], g_w2_l[D * D];
__device__ float g_loss;

// -------------------- helpers --------------------
__device__ __forceinline__ uint32_t smem_u32(const void* p) {
    uint32_t a;
    asm("{ .reg .u64 t; cvta.to.shared.u64 t, %1; cvt.u32.u64 %0, t; }" : "=r"(a) : "l"(p));
    return a;
}
#define SWZ32(o)  ((o) ^ (((o) >> 3) & 0x30))   // 64B rows
#define SWZ128(o) ((o) ^ (((o) >> 3) & 0x70))   // 128B rows
#define LDM4(r0, r1, r2, r3, a) \
    asm volatile("ldmatrix.sync.aligned.m8n8.x4.shared.b16 {%0,%1,%2,%3}, [%4];" \
        : "=r"(r0), "=r"(r1), "=r"(r2), "=r"(r3) : "r"(a))
#define MMA_F16(c, a, b) \
    asm volatile("mma.sync.aligned.m16n8k16.row.col.f32.f16.f16.f32 " \
        "{%0,%1,%2,%3}, {%4,%5,%6,%7}, {%8,%9}, {%0,%1,%2,%3};" \
        : "+f"((c)[0]), "+f"((c)[1]), "+f"((c)[2]), "+f"((c)[3]) \
        : "r"((a)[0]), "r"((a)[1]), "r"((a)[2]), "r"((a)[3]), "r"((b)[0]), "r"((b)[1]))
#define CP_ASYNC16(dst, src) \
    asm volatile("cp.async.cg.shared.global [%0], [%1], 16;" :: "r"(dst), "l"(src))
#define CP_COMMIT() asm volatile("cp.async.commit_group;")
#define CP_WAIT1()  asm volatile("cp.async.wait_group 1;")

__device__ __forceinline__ ull packdi(float d, unsigned j) {
    unsigned u = __float_as_uint(d);
    u = (u & 0x80000000u) ? ~u : (u | 0x80000000u);
    return ((ull)u << 32) | (ull)j;
}
__device__ __forceinline__ float unpackd(ull p) {
    unsigned u = (unsigned)(p >> 32);
    u = (u & 0x80000000u) ? (u & 0x7fffffffu) : ~u;
    return __uint_as_float(u);
}
__device__ __forceinline__ void top2ins(ull& m1, ull& m2, ull p) {
    if (p < m1) { m2 = m1; m1 = p; }
    else if (p < m2) m2 = p;
}

// -------------------- launch 1: init --------------------
__global__ void init_kernel() {
    int r = blockIdx.x * blockDim.x + threadIdx.x;
    if (r < NROWS) {
        g_b1c[r] = ~0ull; g_b2c[r] = ~0ull;
        g_b1f[r] = ~0ull; g_b2f[r] = ~0ull;
    }
}
// -------------------- launch 2: zero scalars --------------------
__global__ void zero_kernel() {
    if (threadIdx.x == 0) { g_loss = 0.f; g_cnt_c = 0; g_cnt_f = 0; }
}

// -------------------- launch 3: fused norms + fp16 hi/lo splits --------------------
__global__ void prep_split(const float* __restrict__ z,
                           const float* __restrict__ ce, const float* __restrict__ fe,
                           const float* __restrict__ w1, const float* __restrict__ w2) {
    int gw = (blockIdx.x * blockDim.x + threadIdx.x) >> 5;
    int lane = threadIdx.x & 31;
    const float* src;
    __half *hi, *lo;
    float* nrm = nullptr;
    if (gw < CB) {
        src = ce + (size_t)gw * D; hi = g_ce_h + (size_t)gw * D; lo = g_ce_l + (size_t)gw * D;
        nrm = g_nsq_c + gw;
    } else if (gw < CB + FB) {
        int r = gw - CB;
        src = fe + (size_t)r * D; hi = g_fe_h + (size_t)r * D; lo = g_fe_l + (size_t)r * D;
        nrm = g_nsq_f + r;
    } else if (gw < CB + FB + NROWS) {
        int r = gw - CB - FB;
        src = z + (size_t)r * 1024; hi = g_zc_h + (size_t)r * D; lo = g_zc_l + (size_t)r * D;
        nrm = g_xnsq_c + r;
    } else if (gw < CB + FB + NROWS + D) {
        int r = gw - CB - FB - NROWS;
        src = w1 + (size_t)r * D; hi = g_w1_h + (size_t)r * D; lo = g_w1_l + (size_t)r * D;
    } else if (gw < CB + FB + NROWS + 2 * D) {
        int r = gw - CB - FB - NROWS - D;
        src = w2 + (size_t)r * D; hi = g_w2_h + (size_t)r * D; lo = g_w2_l + (size_t)r * D;
    } else return;

    float s = 0.f;
    #pragma unroll
    for (int it = 0; it < 4; it++) {
        int c = lane * 4 + it * 128;
        float4 v = *(const float4*)(src + c);
        s += v.x * v.x + v.y * v.y + v.z * v.z + v.w * v.w;
        __half hs[4], ls[4];
        hs[0] = __float2half_rn(v.x); ls[0] = __float2half_rn(v.x - __half2float(hs[0]));
        hs[1] = __float2half_rn(v.y); ls[1] = __float2half_rn(v.y - __half2float(hs[1]));
        hs[2] = __float2half_rn(v.z); ls[2] = __float2half_rn(v.z - __half2float(hs[2]));
        hs[3] = __float2half_rn(v.w); ls[3] = __float2half_rn(v.w - __half2float(hs[3]));
        *(uint2*)(hi + c) = *(uint2*)hs;
        *(uint2*)(lo + c) = *(uint2*)ls;
    }
    if (nrm) {
        #pragma unroll
        for (int o = 16; o; o >>= 1) s += __shfl_xor_sync(0xffffffffu, s, o);
        if (lane == 0) *nrm = s;
    }
}

// -------------------- VQ GEMM: 256 thr, 128x128 tile, KC=64, single-pass hh, 2 CTAs/SM --------------------
__global__ __launch_bounds__(256, 2) void vq_gemm(
    const __half* __restrict__ Ah, const __half* __restrict__ Bh,
    const float* __restrict__ aux, const float* __restrict__ xnsq,
    ull* __restrict__ best1, ull* __restrict__ best2,
    ull* __restrict__ tilemin)
{
    extern __shared__ char sm[];
    __shared__ ull sb1[BM], sb2[BM];
    const int t = threadIdx.x;
    const int lane = t & 31, wid = t >> 5;
    const int warp_m = wid & 1, warp_n = wid >> 1;
    const int row0 = blockIdx.x * BM, col0 = blockIdx.y * BN;
    const uint32_t smb = smem_u32(sm);

    if (t < BM) { sb1[t] = ~0ull; sb2[t] = ~0ull; }

    float acc[4][4][4];
    #pragma unroll
    for (int i = 0; i < 4; i++)
        #pragma unroll
        for (int j = 0; j < 4; j++)
            #pragma unroll
            for (int k = 0; k < 4; k++) acc[i][j][k] = 0.f;

    // loads: 128 rows x 128B each for A and B; thread t -> row t>>1, 64B seg (t&1), 4x16B CPs
    const int lr = t >> 1, ls = t & 1;
    const size_t aoff = (size_t)(row0 + lr) * D + ls * 32;
    const size_t boff = (size_t)(col0 + lr) * D + ls * 32;
    const uint32_t s0 = SWZ128((uint32_t)(lr * 128 + ls * 64));
    const uint32_t s1 = SWZ128((uint32_t)(lr * 128 + ls * 64 + 16));
    const uint32_t s2 = SWZ128((uint32_t)(lr * 128 + ls * 64 + 32));
    const uint32_t s3 = SWZ128((uint32_t)(lr * 128 + ls * 64 + 48));

    // stage: A +0 (16K), B +16384 (16K); stride 32768
    #define VISSUE(c) do { \
        uint32_t bb = smb + (uint32_t)((c) % 3) * 32768u; \
        const int kb = (c) * VKC; \
        CP_ASYNC16(bb + s0, (const char*)(Ah + aoff + kb)); \
        CP_ASYNC16(bb + s1, (const char*)(Ah + aoff + kb + 8)); \
        CP_ASYNC16(bb + s2, (const char*)(Ah + aoff + kb + 16)); \
        CP_ASYNC16(bb + s3, (const char*)(Ah + aoff + kb + 24)); \
        CP_ASYNC16(bb + 16384u + s0, (const char*)(Bh + boff + kb)); \
        CP_ASYNC16(bb + 16384u + s1, (const char*)(Bh + boff + kb + 8)); \
        CP_ASYNC16(bb + 16384u + s2, (const char*)(Bh + boff + kb + 16)); \
        CP_ASYNC16(bb + 16384u + s3, (const char*)(Bh + boff + kb + 24)); \
        CP_COMMIT(); \
    } while (0)

    VISSUE(0);
    VISSUE(1);

    #pragma unroll 1
    for (int c = 0; c < VNCH; c++) {
        const uint32_t bb = smb + (uint32_t)(c % 3) * 32768u;
        CP_WAIT1();
        __syncthreads();
        if (c + 2 < VNCH) VISSUE(c + 2);
        #pragma unroll
        for (int k16 = 0; k16 < 4; k16++) {
            uint32_t bhf[4][2], ah[4][4];
            #pragma unroll
            for (int nt2 = 0; nt2 < 2; nt2++) {
                int nrow = warp_n * 32 + nt2 * 16 + (lane & 7) + ((lane & 16) ? 8 : 0);
                int kbyte = k16 * 32 + ((lane >> 3) & 1) * 16;
                uint32_t off = SWZ128((uint32_t)(nrow * 128 + kbyte));
                LDM4(bhf[nt2 * 2][0], bhf[nt2 * 2][1], bhf[nt2 * 2 + 1][0], bhf[nt2 * 2 + 1][1],
                     bb + 16384u + off);
            }
            #pragma unroll
            for (int mt = 0; mt < 4; mt++) {
                int mrow = warp_m * 64 + mt * 16 + (lane & 15);
                int kbyte = k16 * 32 + (lane >> 4) * 16;
                uint32_t off = SWZ128((uint32_t)(mrow * 128 + kbyte));
                LDM4(ah[mt][0], ah[mt][1], ah[mt][2], ah[mt][3], bb + off);
            }
            #pragma unroll
            for (int mt = 0; mt < 4; mt++)
                #pragma unroll
                for (int nt = 0; nt < 4; nt++) MMA_F16(acc[mt][nt], ah[mt], bhf[nt]);
        }
    }

    const int g = lane >> 2, tg = lane & 3;
    #pragma unroll
    for (int mt = 0; mt < 4; mt++) {
        #pragma unroll
        for (int h8 = 0; h8 < 2; h8++) {
            int lrow2 = warp_m * 64 + mt * 16 + g + h8 * 8;
            float xx = xnsq[row0 + lrow2];
            ull m1 = ~0ull, m2 = ~0ull;
            #pragma unroll
            for (int nt = 0; nt < 4; nt++) {
                int colg = col0 + warp_n * 32 + nt * 8 + tg * 2;
                float d0 = __fadd_rn(__fadd_rn(xx, aux[colg]), -2.f * acc[mt][nt][h8 * 2 + 0]);
                float d1 = __fadd_rn(__fadd_rn(xx, aux[colg + 1]), -2.f * acc[mt][nt][h8 * 2 + 1]);
                top2ins(m1, m2, packdi(d0, (unsigned)colg));
                top2ins(m1, m2, packdi(d1, (unsigned)(colg + 1)));
            }
            #pragma unroll
            for (int o = 1; o <= 2; o <<= 1) {
                ull o1 = __shfl_xor_sync(0xffffffffu, m1, o);
                ull o2 = __shfl_xor_sync(0xffffffffu, m2, o);
                ull n1 = o1 < m1 ? o1 : m1;
                ull hi = o1 > m1 ? o1 : m1;
                ull lo2 = o2 < m2 ? o2 : m2;
                m2 = hi < lo2 ? hi : lo2;
                m1 = n1;
            }
            if (tg == 0) {
                ull old = atomicMin(&sb1[lrow2], m1);
                atomicMin(&sb2[lrow2], old > m1 ? old : m1);
                atomicMin(&sb2[lrow2], m2);
            }
        }
    }
    __syncthreads();
    if (t < BM) {
        ull v1 = sb1[t], v2 = sb2[t];
        ull old = atomicMin(&best1[row0 + t], v1);
        atomicMin(&best2[row0 + t], old > v1 ? old : v1);
        atomicMin(&best2[row0 + t], v2);
        tilemin[(size_t)(row0 + t) * MAXTILES + blockIdx.y] = v1;
    }
    #undef VISSUE
}

// -------------------- MLP GEMM: 3-pass emulated fp32 (R13 shape, KC=32) --------------------
__global__ __launch_bounds__(256, 2) void mlp_gemm(
    const __half* __restrict__ Ah, const __half* __restrict__ Al,
    const __half* __restrict__ Bh, const __half* __restrict__ Bl,
    const float* __restrict__ aux, float* __restrict__ out)
{
    extern __shared__ char sm[];
    const int t = threadIdx.x;
    const int lane = t & 31, wid = t >> 5;
    const int warp_m = wid & 1, warp_n = wid >> 1;
    const int row0 = blockIdx.x * BM, col0 = blockIdx.y * BN;
    const uint32_t smb = smem_u32(sm);

    float acc[4][4][4];
    #pragma unroll
    for (int i = 0; i < 4; i++)
        #pragma unroll
        for (int j = 0; j < 4; j++)
            #pragma unroll
            for (int k = 0; k < 4; k++) acc[i][j][k] = 0.f;

    const int lrow = t >> 1, lh = t & 1;
    const size_t aoff = (size_t)(row0 + lrow) * D + lh * 16;
    const size_t boff = (size_t)(col0 + lrow) * D + lh * 16;
    const uint32_t st0 = SWZ32((uint32_t)(lrow * 64 + lh * 32));
    const uint32_t st1 = SWZ32((uint32_t)(lrow * 64 + lh * 32 + 16));

    #define MISSUE(c) do { \
        uint32_t bb = smb + (uint32_t)((c) % 3) * 32768u; \
        const int kb = (c) * KC; \
        CP_ASYNC16(bb + st0, (const char*)(Ah + aoff + kb)); \
        CP_ASYNC16(bb + st1, (const char*)(Ah + aoff + kb + 8)); \
        CP_ASYNC16(bb + 8192u  + st0, (const char*)(Al + aoff + kb)); \
        CP_ASYNC16(bb + 8192u  + st1, (const char*)(Al + aoff + kb + 8)); \
        CP_ASYNC16(bb + 16384u + st0, (const char*)(Bh + boff + kb)); \
        CP_ASYNC16(bb + 16384u + st1, (const char*)(Bh + boff + kb + 8)); \
        CP_ASYNC16(bb + 24576u + st0, (const char*)(Bl + boff + kb)); \
        CP_ASYNC16(bb + 24576u + st1, (const char*)(Bl + boff + kb + 8)); \
        CP_COMMIT(); \
    } while (0)

    MISSUE(0);
    MISSUE(1);

    #pragma unroll 1
    for (int c = 0; c < NCH; c++) {
        const uint32_t bb = smb + (uint32_t)(c % 3) * 32768u;
        CP_WAIT1();
        __syncthreads();
        if (c + 2 < NCH) MISSUE(c + 2);
        #pragma unroll
        for (int k16 = 0; k16 < 2; k16++) {
            uint32_t bhf[4][2], blf[4][2], ah[4][4], al[4][4];
            #pragma unroll
            for (int nt2 = 0; nt2 < 2; nt2++) {
                int nrow = warp_n * 32 + nt2 * 16 + (lane & 7) + ((lane & 16) ? 8 : 0);
                int kbyte = k16 * 32 + ((lane >> 3) & 1) * 16;
                uint32_t off = SWZ32((uint32_t)(nrow * 64 + kbyte));
                LDM4(bhf[nt2 * 2][0], bhf[nt2 * 2][1], bhf[nt2 * 2 + 1][0], bhf[nt2 * 2 + 1][1], bb + 16384u + off);
            }
            #pragma unroll
            for (int mt = 0; mt < 4; mt++) {
                int mrow = warp_m * 64 + mt * 16 + (lane & 15);
                int kbyte = k16 * 32 + (lane >> 4) * 16;
                uint32_t off = SWZ32((uint32_t)(mrow * 64 + kbyte));
                LDM4(ah[mt][0], ah[mt][1], ah[mt][2], ah[mt][3], bb + off);
            }
            #pragma unroll
            for (int nt2 = 0; nt2 < 2; nt2++) {
                int nrow = warp_n * 32 + nt2 * 16 + (lane & 7) + ((lane & 16) ? 8 : 0);
                int kbyte = k16 * 32 + ((lane >> 3) & 1) * 16;
                uint32_t off = SWZ32((uint32_t)(nrow * 64 + kbyte));
                LDM4(blf[nt2 * 2][0], blf[nt2 * 2][1], blf[nt2 * 2 + 1][0], blf[nt2 * 2 + 1][1], bb + 24576u + off);
            }
            #pragma unroll
            for (int mt = 0; mt < 4; mt++)
                #pragma unroll
                for (int nt = 0; nt < 4; nt++) MMA_F16(acc[mt][nt], ah[mt], bhf[nt]);
            #pragma unroll
            for (int mt = 0; mt < 4; mt++) {
                int mrow = warp_m * 64 + mt * 16 + (lane & 15);
                int kbyte = k16 * 32 + (lane >> 4) * 16;
                uint32_t off = SWZ32((uint32_t)(mrow * 64 + kbyte));
                LDM4(al[mt][0], al[mt][1], al[mt][2], al[mt][3], bb + 8192u + off);
            }
            #pragma unroll
            for (int mt = 0; mt < 4; mt++)
                #pragma unroll
                for (int nt = 0; nt < 4; nt++) MMA_F16(acc[mt][nt], ah[mt], blf[nt]);
            #pragma unroll
            for (int mt = 0; mt < 4; mt++)
                #pragma unroll
                for (int nt = 0; nt < 4; nt++) MMA_F16(acc[mt][nt], al[mt], bhf[nt]);
        }
    }

    const int g = lane >> 2, tg = lane & 3;
    #pragma unroll
    for (int mt = 0; mt < 4; mt++) {
        #pragma unroll
        for (int h8 = 0; h8 < 2; h8++) {
            int row = row0 + warp_m * 64 + mt * 16 + g + h8 * 8;
            #pragma unroll
            for (int nt = 0; nt < 4; nt++) {
                int colg = col0 + warp_n * 32 + nt * 8 + tg * 2;
                float2 o2 = make_float2(acc[mt][nt][h8 * 2 + 0] + aux[colg],
                                        acc[mt][nt][h8 * 2 + 1] + aux[colg + 1]);
                *(float2*)&out[(size_t)row * D + colg] = o2;
            }
        }
    }
    #undef MISSUE
}

// -------------------- flag: compact near-tie rows --------------------
__global__ void flag_kernel(const ull* __restrict__ b1, const ull* __restrict__ b2,
                            int* __restrict__ idx, int* __restrict__ list, int* __restrict__ cnt) {
    int r = blockIdx.x * blockDim.x + threadIdx.x;
    if (r >= NROWS) return;
    ull p1 = b1[r];
    idx[r] = (int)(p1 & 0xffffffffu);
    g_ex[r] = ~0ull;
    if (unpackd(b2[r]) - unpackd(p1) <= THRESH) {
        int pos = atomicAdd(cnt, 1);
        list[pos] = r;
    }
}

// -------------------- exact re-decide, tile-pruned (128-wide tiles) --------------------
__global__ void exact_kernel(const float* __restrict__ x, int ldx,
                             const float* __restrict__ emb, int ntiles,
                             const float* __restrict__ nsq, const float* __restrict__ xnsq,
                             const int* __restrict__ list, const int* __restrict__ cnt,
                             const ull* __restrict__ b1, const ull* __restrict__ tilemin,
                             ull* __restrict__ ex) {
    int i = blockIdx.x;
    if (i >= *cnt) return;
    int r = list[i];
    __shared__ float xs[D];
    __shared__ ull wmin[8];
    const int t = threadIdx.x, lane = t & 31, w = t >> 5;
    if (t < 128) ((float4*)xs)[t] = *(const float4*)(x + (size_t)r * ldx + t * 4);
    if (t < 8) wmin[t] = ~0ull;
    __syncthreads();
    float xx = xnsq[r];
    float dcut = unpackd(b1[r]) + 2.f * THRESH;
    ull m = ~0ull;
    for (int tt = 0; tt < ntiles; tt++) {
        if (unpackd(tilemin[(size_t)r * MAXTILES + tt]) > dcut) continue;
        for (int cc = w; cc < BN; cc += 8) {
            int j = tt * BN + cc;
            const float* e = emb + (size_t)j * D;
            float s = 0.f;
            for (int k = lane; k < D; k += 32) s = fmaf(e[k], xs[k], s);
            #pragma unroll
            for (int o = 16; o; o >>= 1) s += __shfl_xor_sync(0xffffffffu, s, o);
            if (lane == 0) {
                float d = __fadd_rn(__fadd_rn(xx, nsq[j]), -2.f * s);
                ull p = packdi(d, (unsigned)j);
                if (p < m) m = p;
            }
        }
    }
    if (lane == 0) wmin[w] = m;
    __syncthreads();
    if (t == 0) {
        ull mm = wmin[0];
        #pragma unroll
        for (int k = 1; k < 8; k++) if (wmin[k] < mm) mm = wmin[k];
        ex[r] = mm;
    }
}

// -------------------- select exact winners --------------------
__global__ void sel_kernel(const int* __restrict__ list, const int* __restrict__ cnt,
                           const ull* __restrict__ ex, int* __restrict__ idx) {
    int i = blockIdx.x * blockDim.x + threadIdx.x;
    if (i < *cnt) { int r = list[i]; idx[r] = (int)(ex[r] & 0xffffffffu); }
}

// -------------------- gather q = emb[idx] (+ split), loss --------------------
__global__ void gather_loss(const float* __restrict__ emb, const int* __restrict__ idx,
                            const float* __restrict__ x, int ldx, float* __restrict__ q,
                            __half* __restrict__ qh, __half* __restrict__ ql) {
    int r = blockIdx.x;
    int j = idx[r];
    const float* e = emb + (size_t)j * D;
    const float* xr = x + (size_t)r * ldx;
    float* qr = q + (size_t)r * D;
    float ls = 0.f;
    for (int k = threadIdx.x; k < D; k += blockDim.x) {
        float ev = e[k];
        qr[k] = ev;
        __half hh = __float2half_rn(ev);
        qh[(size_t)r * D + k] = hh;
        ql[(size_t)r * D + k] = __float2half_rn(ev - __half2float(hh));
        float dd = ev - xr[k];
        ls += dd * dd;
    }
    #pragma unroll
    for (int o = 16; o; o >>= 1) ls += __shfl_xor_sync(0xffffffffu, ls, o);
    __shared__ float ws[8];
    int w = threadIdx.x >> 5;
    if ((threadIdx.x & 31) == 0) ws[w] = ls;
    __syncthreads();
    if (threadIdx.x == 0) {
        float s = 0.f;
        for (int i = 0; i < 8; i++) s += ws[i];
        atomicAdd(&g_loss, s);
    }
}

// -------------------- LayerNorm + leakyReLU + fused follow-up --------------------
template <int MODE>
__global__ void ln_kernel(const float* __restrict__ h,
                          const float* __restrict__ g, const float* __restrict__ be,
                          const float* __restrict__ z,
                          const float* __restrict__ gc_raw, const float* __restrict__ gf_raw,
                          float* __restrict__ out)
{
    int r = blockIdx.x;
    int j = threadIdx.x;
    float hv = h[(size_t)r * D + j];
    float s = hv, sq = hv * hv;
    #pragma unroll
    for (int o = 16; o; o >>= 1) {
        s += __shfl_xor_sync(0xffffffffu, s, o);
        sq += __shfl_xor_sync(0xffffffffu, sq, o);
    }
    __shared__ float s1[16], s2[16];
    int w = j >> 5, lane = j & 31;
    if (lane == 0) { s1[w] = s; s2[w] = sq; }
    __syncthreads();
    if (w == 0) {
        s = (lane < 16) ? s1[lane] : 0.f;
        sq = (lane < 16) ? s2[lane] : 0.f;
        #pragma unroll
        for (int o = 8; o; o >>= 1) {
            s += __shfl_xor_sync(0xffffffffu, s, o);
            sq += __shfl_xor_sync(0xffffffffu, sq, o);
        }
        if (lane == 0) { s1[0] = s; s2[0] = sq; }
    }
    __syncthreads();
    float mean = s1[0] * (1.f / D);
    float var = s2[0] * (1.f / D) - mean * mean;
    float y = (hv - mean) * rsqrtf(var + 1e-5f) * g[j] + be[j];
    float act = y > 0.f ? y : 0.1f * y;
    float gcv = 1.f / (1.f + expf(-gc_raw[0]));

    if (MODE == 0) {
        float rv = z[(size_t)r * 1024 + D + j] - gcv * act;
        g_ci[(size_t)r * D + j] = act;
        g_res[(size_t)r * D + j] = rv;
        __half hh = __float2half_rn(rv);
        g_res_h[(size_t)r * D + j] = hh;
        g_res_l[(size_t)r * D + j] = __float2half_rn(rv - __half2float(hh));
        float rq = rv * rv;
        #pragma unroll
        for (int o = 16; o; o >>= 1) rq += __shfl_xor_sync(0xffffffffu, rq, o);
        __syncthreads();
        if (lane == 0) s1[w] = rq;
        __syncthreads();
        if (j == 0) {
            float tt = 0.f;
            #pragma unroll
            for (int i = 0; i < 16; i++) tt += s1[i];
            g_xnsq_f[r] = tt;
        }
    } else {
        float gfv = 1.f / (1.f + expf(-gf_raw[0]));
        out[(size_t)r * 1024 + j] = g_qc[(size_t)r * D + j] + 0.1f * gfv * act;
        out[(size_t)r * 1024 + D + j] = g_qf[(size_t)r * D + j] + gcv * g_ci[(size_t)r * D + j];
        if (r == 0 && j == 0)
            out[(size_t)NROWS * 1024] = 1.25f * g_loss / (float)((size_t)NROWS * D);
    }
}

// -------------------- launch --------------------
#define SYMADDR(p, s) cudaGetSymbolAddress((void**)&p, s)

extern "C" void kernel_launch(void* const* d_in, const int* in_sizes, int n_in,
                              void* d_out, int out_size) {
    const float* z      = (const float*)d_in[0];
    const float* ce     = (const float*)d_in[1];
    const float* fe     = (const float*)d_in[2];
    const float* w_c2f  = (const float*)d_in[3];
    const float* b_c2f  = (const float*)d_in[4];
    const float* g_c2f  = (const float*)d_in[5];
    const float* be_c2f = (const float*)d_in[6];
    const float* w_f2c  = (const float*)d_in[7];
    const float* b_f2c  = (const float*)d_in[8];
    const float* g_f2c  = (const float*)d_in[9];
    const float* be_f2c = (const float*)d_in[10];
    const float* gc_raw = (const float*)d_in[11];
    const float* gf_raw = (const float*)d_in[12];
    float* out = (float*)d_out;

    float *nsq_c, *nsq_f, *xnsq_c, *xnsq_f, *qc, *qf, *res, *h;
    ull *b1c, *b2c, *b1f, *b2f, *ex, *tmin;
    int *idx_c, *idx_f, *list, *cnt_c, *cnt_f;
    __half *zc_h, *zc_l, *ce_h, *ce_l, *fe_h, *fe_l, *res_h, *res_l, *q_h, *q_l;
    __half *w1_h, *w1_l, *w2_h, *w2_l;
    SYMADDR(nsq_c, g_nsq_c);   SYMADDR(nsq_f, g_nsq_f);
    SYMADDR(xnsq_c, g_xnsq_c); SYMADDR(xnsq_f, g_xnsq_f);
    SYMADDR(b1c, g_b1c); SYMADDR(b2c, g_b2c); SYMADDR(b1f, g_b1f); SYMADDR(b2f, g_b2f);
    SYMADDR(ex, g_ex); SYMADDR(tmin, g_tmin);
    SYMADDR(idx_c, g_idx_c); SYMADDR(idx_f, g_idx_f);
    SYMADDR(list, g_list);
    SYMADDR(cnt_c, g_cnt_c); SYMADDR(cnt_f, g_cnt_f);
    SYMADDR(qc, g_qc); SYMADDR(qf, g_qf); SYMADDR(res, g_res); SYMADDR(h, g_h);
    SYMADDR(zc_h, g_zc_h); SYMADDR(zc_l, g_zc_l);
    SYMADDR(ce_h, g_ce_h); SYMADDR(ce_l, g_ce_l);
    SYMADDR(fe_h, g_fe_h); SYMADDR(fe_l, g_fe_l);
    SYMADDR(res_h, g_res_h); SYMADDR(res_l, g_res_l);
    SYMADDR(q_h, g_q_h); SYMADDR(q_l, g_q_l);
    SYMADDR(w1_h, g_w1_h); SYMADDR(w1_l, g_w1_l);
    SYMADDR(w2_h, g_w2_h); SYMADDR(w2_l, g_w2_l);

    cudaFuncSetAttribute(vq_gemm, cudaFuncAttributeMaxDynamicSharedMemorySize, SMEM_DYN);
    cudaFuncSetAttribute(mlp_gemm, cudaFuncAttributeMaxDynamicSharedMemorySize, SMEM_DYN);

    init_kernel<<<NROWS / 256, 256>>>();
    zero_kernel<<<1, 32>>>();
    {
        int warps = CB + FB + NROWS + 2 * D;
        prep_split<<<(warps * 32 + 255) / 256, 256>>>(z, ce, fe, w_c2f, w_f2c);
    }
    // coarse VQ  (launch #4 — profiled)
    vq_gemm<<<dim3(NROWS / BM, CB / BN), 256, SMEM_DYN>>>(zc_h, ce_h, nsq_c, xnsq_c, b1c, b2c, tmin);
    flag_kernel<<<NROWS / 256, 256>>>(b1c, b2c, idx_c, list, cnt_c);
    exact_kernel<<<NROWS, 256>>>(z, 1024, ce, CB / BN, nsq_c, xnsq_c, list, cnt_c, b1c, tmin, ex);
    sel_kernel<<<NROWS / 256, 256>>>(list, cnt_c, ex, idx_c);
    gather_loss<<<NROWS, 256>>>(ce, idx_c, z, 1024, qc, q_h, q_l);
    // MLP c2f
    mlp_gemm<<<dim3(NROWS / BM, D / BN), 256, SMEM_DYN>>>(q_h, q_l, w1_h, w1_l, b_c2f, h);
    ln_kernel<0><<<NROWS, 512>>>(h, g_c2f, be_c2f, z, gc_raw, gf_raw, nullptr);
    // fine VQ
    vq_gemm<<<dim3(NROWS / BM, FB / BN), 256, SMEM_DYN>>>(res_h, fe_h, nsq_f, xnsq_f, b1f, b2f, tmin);
    flag_kernel<<<NROWS / 256, 256>>>(b1f, b2f, idx_f, list, cnt_f);
    exact_kernel<<<NROWS, 256>>>(res, D, fe, FB / BN, nsq_f, xnsq_f, list, cnt_f, b1f, tmin, ex);
    sel_kernel<<<NROWS / 256, 256>>>(list, cnt_f, ex, idx_f);
    gather_loss<<<NROWS, 256>>>(fe, idx_f, res, D, qf, q_h, q_l);
    // MLP f2c
    mlp_gemm<<<dim3(NROWS / BM, D / BN), 256, SMEM_DYN>>>(q_h, q_l, w2_h, w2_l, b_f2c, h);
    ln_kernel<1><<<NROWS, 512>>>(h, g_f2c, be_f2c, z, gc_raw, gf_raw, out);
}

// round 16
// speedup vs baseline: 1.2358x; 1.0481x over previous
#include <cuda_runtime.h>
#include <cuda_fp16.h>
#include <cstdint>
#include <math.h>

#define NROWS 8192
#define D     512
#define CB    4096
#define FB    8192
#define BM    128
#define BN    128
#define KC    32
#define NCH   (D / KC)
#define VKC   64
#define VNCH  (D / VKC)
#define THRESH 4e-3f
#define SMEM_DYN 98304
#define MAXTILES 64

typedef unsigned long long ull;

// -------------------- device scratch --------------------
__device__ float g_nsq_c[CB], g_nsq_f[FB];
__device__ float g_xnsq_c[NROWS], g_xnsq_f[NROWS];
__device__ ull   g_b1c[NROWS], g_b2c[NROWS], g_b1f[NROWS], g_b2f[NROWS];
__device__ ull   g_ex[NROWS];
__device__ ull   g_tmin[NROWS * MAXTILES];
__device__ int   g_idx_c[NROWS], g_idx_f[NROWS];
__device__ int   g_list[NROWS];
__device__ int   g_cnt_c, g_cnt_f;
__device__ float g_qc[NROWS * D], g_qf[NROWS * D];
__device__ float g_ci[NROWS * D], g_res[NROWS * D], g_h[NROWS * D];
__device__ __half g_zc_h[NROWS * D];
__device__ __half g_ce_h[CB * D];
__device__ __half g_fe_h[FB * D];
__device__ __half g_res_h[NROWS * D];
__device__ __half g_q_h[NROWS * D], g_q_l[NROWS * D];
__device__ __half g_w1_h[D * D], g_w1_l[D * D], g_w2_h[D * D], g_w2_l[D * D];
__device__ float g_loss;

// -------------------- helpers --------------------
__device__ __forceinline__ uint32_t smem_u32(const void* p) {
    uint32_t a;
    asm("{ .reg .u64 t; cvta.to.shared.u64 t, %1; cvt.u32.u64 %0, t; }" : "=r"(a) : "l"(p));
    return a;
}
#define SWZ32(o)  ((o) ^ (((o) >> 3) & 0x30))   // 64B rows
#define SWZ128(o) ((o) ^ (((o) >> 3) & 0x70))   // 128B rows
#define LDM4(r0, r1, r2, r3, a) \
    asm volatile("ldmatrix.sync.aligned.m8n8.x4.shared.b16 {%0,%1,%2,%3}, [%4];" \
        : "=r"(r0), "=r"(r1), "=r"(r2), "=r"(r3) : "r"(a))
#define MMA_F16(c, a, b) \
    asm volatile("mma.sync.aligned.m16n8k16.row.col.f32.f16.f16.f32 " \
        "{%0,%1,%2,%3}, {%4,%5,%6,%7}, {%8,%9}, {%0,%1,%2,%3};" \
        : "+f"((c)[0]), "+f"((c)[1]), "+f"((c)[2]), "+f"((c)[3]) \
        : "r"((a)[0]), "r"((a)[1]), "r"((a)[2]), "r"((a)[3]), "r"((b)[0]), "r"((b)[1]))
#define CP_ASYNC16(dst, src) \
    asm volatile("cp.async.cg.shared.global [%0], [%1], 16;" :: "r"(dst), "l"(src))
#define CP_COMMIT() asm volatile("cp.async.commit_group;")
#define CP_WAIT1()  asm volatile("cp.async.wait_group 1;")

__device__ __forceinline__ ull packdi(float d, unsigned j) {
    unsigned u = __float_as_uint(d);
    u = (u & 0x80000000u) ? ~u : (u | 0x80000000u);
    return ((ull)u << 32) | (ull)j;
}
__device__ __forceinline__ float unpackd(ull p) {
    unsigned u = (unsigned)(p >> 32);
    u = (u & 0x80000000u) ? (u & 0x7fffffffu) : ~u;
    return __uint_as_float(u);
}
__device__ __forceinline__ void top2ins(ull& m1, ull& m2, ull p) {
    if (p < m1) { m2 = m1; m1 = p; }
    else if (p < m2) m2 = p;
}

// -------------------- launch 1: init best arrays + scalars --------------------
__global__ void init_kernel() {
    int r = blockIdx.x * blockDim.x + threadIdx.x;
    if (r < NROWS) {
        g_b1c[r] = ~0ull; g_b2c[r] = ~0ull;
        g_b1f[r] = ~0ull; g_b2f[r] = ~0ull;
    }
    if (r == 0) { g_loss = 0.f; g_cnt_c = 0; g_cnt_f = 0; }
}

// -------------------- launch 2: fused norms + fp16 splits (hi only except weights) --------------------
__global__ void prep_split(const float* __restrict__ z,
                           const float* __restrict__ ce, const float* __restrict__ fe,
                           const float* __restrict__ w1, const float* __restrict__ w2) {
    int gw = (blockIdx.x * blockDim.x + threadIdx.x) >> 5;
    int lane = threadIdx.x & 31;
    const float* src;
    __half *hi, *lo = nullptr;
    float* nrm = nullptr;
    if (gw < CB) {
        src = ce + (size_t)gw * D; hi = g_ce_h + (size_t)gw * D; nrm = g_nsq_c + gw;
    } else if (gw < CB + FB) {
        int r = gw - CB;
        src = fe + (size_t)r * D; hi = g_fe_h + (size_t)r * D; nrm = g_nsq_f + r;
    } else if (gw < CB + FB + NROWS) {
        int r = gw - CB - FB;
        src = z + (size_t)r * 1024; hi = g_zc_h + (size_t)r * D; nrm = g_xnsq_c + r;
    } else if (gw < CB + FB + NROWS + D) {
        int r = gw - CB - FB - NROWS;
        src = w1 + (size_t)r * D; hi = g_w1_h + (size_t)r * D; lo = g_w1_l + (size_t)r * D;
    } else if (gw < CB + FB + NROWS + 2 * D) {
        int r = gw - CB - FB - NROWS - D;
        src = w2 + (size_t)r * D; hi = g_w2_h + (size_t)r * D; lo = g_w2_l + (size_t)r * D;
    } else return;

    float s = 0.f;
    #pragma unroll
    for (int it = 0; it < 4; it++) {
        int c = lane * 4 + it * 128;
        float4 v = *(const float4*)(src + c);
        s += v.x * v.x + v.y * v.y + v.z * v.z + v.w * v.w;
        __half hs[4];
        hs[0] = __float2half_rn(v.x); hs[1] = __float2half_rn(v.y);
        hs[2] = __float2half_rn(v.z); hs[3] = __float2half_rn(v.w);
        *(uint2*)(hi + c) = *(uint2*)hs;
        if (lo) {
            __half ls[4];
            ls[0] = __float2half_rn(v.x - __half2float(hs[0]));
            ls[1] = __float2half_rn(v.y - __half2float(hs[1]));
            ls[2] = __float2half_rn(v.z - __half2float(hs[2]));
            ls[3] = __float2half_rn(v.w - __half2float(hs[3]));
            *(uint2*)(lo + c) = *(uint2*)ls;
        }
    }
    if (nrm) {
        #pragma unroll
        for (int o = 16; o; o >>= 1) s += __shfl_xor_sync(0xffffffffu, s, o);
        if (lane == 0) *nrm = s;
    }
}

// -------------------- VQ GEMM: 256 thr, 128x128 tile, KC=64, single-pass hh, 2 CTAs/SM --------------------
__global__ __launch_bounds__(256, 2) void vq_gemm(
    const __half* __restrict__ Ah, const __half* __restrict__ Bh,
    const float* __restrict__ aux, const float* __restrict__ xnsq,
    ull* __restrict__ best1, ull* __restrict__ best2,
    ull* __restrict__ tilemin)
{
    extern __shared__ char sm[];
    __shared__ ull sb1[BM], sb2[BM];
    const int t = threadIdx.x;
    const int lane = t & 31, wid = t >> 5;
    const int warp_m = wid & 1, warp_n = wid >> 1;
    const int row0 = blockIdx.x * BM, col0 = blockIdx.y * BN;
    const uint32_t smb = smem_u32(sm);

    if (t < BM) { sb1[t] = ~0ull; sb2[t] = ~0ull; }

    float acc[4][4][4];
    #pragma unroll
    for (int i = 0; i < 4; i++)
        #pragma unroll
        for (int j = 0; j < 4; j++)
            #pragma unroll
            for (int k = 0; k < 4; k++) acc[i][j][k] = 0.f;

    const int lr = t >> 1, ls = t & 1;
    const size_t aoff = (size_t)(row0 + lr) * D + ls * 32;
    const size_t boff = (size_t)(col0 + lr) * D + ls * 32;
    const uint32_t s0 = SWZ128((uint32_t)(lr * 128 + ls * 64));
    const uint32_t s1 = SWZ128((uint32_t)(lr * 128 + ls * 64 + 16));
    const uint32_t s2 = SWZ128((uint32_t)(lr * 128 + ls * 64 + 32));
    const uint32_t s3 = SWZ128((uint32_t)(lr * 128 + ls * 64 + 48));

    #define VISSUE(c) do { \
        uint32_t bb = smb + (uint32_t)((c) % 3) * 32768u; \
        const int kb = (c) * VKC; \
        CP_ASYNC16(bb + s0, (const char*)(Ah + aoff + kb)); \
        CP_ASYNC16(bb + s1, (const char*)(Ah + aoff + kb + 8)); \
        CP_ASYNC16(bb + s2, (const char*)(Ah + aoff + kb + 16)); \
        CP_ASYNC16(bb + s3, (const char*)(Ah + aoff + kb + 24)); \
        CP_ASYNC16(bb + 16384u + s0, (const char*)(Bh + boff + kb)); \
        CP_ASYNC16(bb + 16384u + s1, (const char*)(Bh + boff + kb + 8)); \
        CP_ASYNC16(bb + 16384u + s2, (const char*)(Bh + boff + kb + 16)); \
        CP_ASYNC16(bb + 16384u + s3, (const char*)(Bh + boff + kb + 24)); \
        CP_COMMIT(); \
    } while (0)

    VISSUE(0);
    VISSUE(1);

    #pragma unroll 1
    for (int c = 0; c < VNCH; c++) {
        const uint32_t bb = smb + (uint32_t)(c % 3) * 32768u;
        CP_WAIT1();
        __syncthreads();
        if (c + 2 < VNCH) VISSUE(c + 2);
        #pragma unroll
        for (int k16 = 0; k16 < 4; k16++) {
            uint32_t bhf[4][2], ah[4][4];
            #pragma unroll
            for (int nt2 = 0; nt2 < 2; nt2++) {
                int nrow = warp_n * 32 + nt2 * 16 + (lane & 7) + ((lane & 16) ? 8 : 0);
                int kbyte = k16 * 32 + ((lane >> 3) & 1) * 16;
                uint32_t off = SWZ128((uint32_t)(nrow * 128 + kbyte));
                LDM4(bhf[nt2 * 2][0], bhf[nt2 * 2][1], bhf[nt2 * 2 + 1][0], bhf[nt2 * 2 + 1][1],
                     bb + 16384u + off);
            }
            #pragma unroll
            for (int mt = 0; mt < 4; mt++) {
                int mrow = warp_m * 64 + mt * 16 + (lane & 15);
                int kbyte = k16 * 32 + (lane >> 4) * 16;
                uint32_t off = SWZ128((uint32_t)(mrow * 128 + kbyte));
                LDM4(ah[mt][0], ah[mt][1], ah[mt][2], ah[mt][3], bb + off);
            }
            #pragma unroll
            for (int mt = 0; mt < 4; mt++)
                #pragma unroll
                for (int nt = 0; nt < 4; nt++) MMA_F16(acc[mt][nt], ah[mt], bhf[nt]);
        }
    }

    const int g = lane >> 2, tg = lane & 3;
    #pragma unroll
    for (int mt = 0; mt < 4; mt++) {
        #pragma unroll
        for (int h8 = 0; h8 < 2; h8++) {
            int lrow2 = warp_m * 64 + mt * 16 + g + h8 * 8;
            float xx = xnsq[row0 + lrow2];
            ull m1 = ~0ull, m2 = ~0ull;
            #pragma unroll
            for (int nt = 0; nt < 4; nt++) {
                int colg = col0 + warp_n * 32 + nt * 8 + tg * 2;
                float d0 = __fadd_rn(__fadd_rn(xx, aux[colg]), -2.f * acc[mt][nt][h8 * 2 + 0]);
                float d1 = __fadd_rn(__fadd_rn(xx, aux[colg + 1]), -2.f * acc[mt][nt][h8 * 2 + 1]);
                top2ins(m1, m2, packdi(d0, (unsigned)colg));
                top2ins(m1, m2, packdi(d1, (unsigned)(colg + 1)));
            }
            #pragma unroll
            for (int o = 1; o <= 2; o <<= 1) {
                ull o1 = __shfl_xor_sync(0xffffffffu, m1, o);
                ull o2 = __shfl_xor_sync(0xffffffffu, m2, o);
                ull n1 = o1 < m1 ? o1 : m1;
                ull hi = o1 > m1 ? o1 : m1;
                ull lo2 = o2 < m2 ? o2 : m2;
                m2 = hi < lo2 ? hi : lo2;
                m1 = n1;
            }
            if (tg == 0) {
                ull old = atomicMin(&sb1[lrow2], m1);
                atomicMin(&sb2[lrow2], old > m1 ? old : m1);
                atomicMin(&sb2[lrow2], m2);
            }
        }
    }
    __syncthreads();
    if (t < BM) {
        ull v1 = sb1[t], v2 = sb2[t];
        ull old = atomicMin(&best1[row0 + t], v1);
        atomicMin(&best2[row0 + t], old > v1 ? old : v1);
        atomicMin(&best2[row0 + t], v2);
        tilemin[(size_t)(row0 + t) * MAXTILES + blockIdx.y] = v1;
    }
    #undef VISSUE
}

// -------------------- MLP GEMM: PASSES=3 (c2f, emulated fp32) or 1 (f2c, hh only) --------------------
template <int PASSES>
__global__ __launch_bounds__(256, 2) void mlp_gemm(
    const __half* __restrict__ Ah, const __half* __restrict__ Al,
    const __half* __restrict__ Bh, const __half* __restrict__ Bl,
    const float* __restrict__ aux, float* __restrict__ out)
{
    extern __shared__ char sm[];
    const int t = threadIdx.x;
    const int lane = t & 31, wid = t >> 5;
    const int warp_m = wid & 1, warp_n = wid >> 1;
    const int row0 = blockIdx.x * BM, col0 = blockIdx.y * BN;
    const uint32_t smb = smem_u32(sm);

    float acc[4][4][4];
    #pragma unroll
    for (int i = 0; i < 4; i++)
        #pragma unroll
        for (int j = 0; j < 4; j++)
            #pragma unroll
            for (int k = 0; k < 4; k++) acc[i][j][k] = 0.f;

    const int lrow = t >> 1, lh = t & 1;
    const size_t aoff = (size_t)(row0 + lrow) * D + lh * 16;
    const size_t boff = (size_t)(col0 + lrow) * D + lh * 16;
    const uint32_t st0 = SWZ32((uint32_t)(lrow * 64 + lh * 32));
    const uint32_t st1 = SWZ32((uint32_t)(lrow * 64 + lh * 32 + 16));

    #define MISSUE(c) do { \
        uint32_t bb = smb + (uint32_t)((c) % 3) * 32768u; \
        const int kb = (c) * KC; \
        CP_ASYNC16(bb + st0, (const char*)(Ah + aoff + kb)); \
        CP_ASYNC16(bb + st1, (const char*)(Ah + aoff + kb + 8)); \
        CP_ASYNC16(bb + 16384u + st0, (const char*)(Bh + boff + kb)); \
        CP_ASYNC16(bb + 16384u + st1, (const char*)(Bh + boff + kb + 8)); \
        if (PASSES == 3) { \
            CP_ASYNC16(bb + 8192u  + st0, (const char*)(Al + aoff + kb)); \
            CP_ASYNC16(bb + 8192u  + st1, (const char*)(Al + aoff + kb + 8)); \
            CP_ASYNC16(bb + 24576u + st0, (const char*)(Bl + boff + kb)); \
            CP_ASYNC16(bb + 24576u + st1, (const char*)(Bl + boff + kb + 8)); \
        } \
        CP_COMMIT(); \
    } while (0)

    MISSUE(0);
    MISSUE(1);

    #pragma unroll 1
    for (int c = 0; c < NCH; c++) {
        const uint32_t bb = smb + (uint32_t)(c % 3) * 32768u;
        CP_WAIT1();
        __syncthreads();
        if (c + 2 < NCH) MISSUE(c + 2);
        #pragma unroll
        for (int k16 = 0; k16 < 2; k16++) {
            uint32_t bhf[4][2], ah[4][4];
            #pragma unroll
            for (int nt2 = 0; nt2 < 2; nt2++) {
                int nrow = warp_n * 32 + nt2 * 16 + (lane & 7) + ((lane & 16) ? 8 : 0);
                int kbyte = k16 * 32 + ((lane >> 3) & 1) * 16;
                uint32_t off = SWZ32((uint32_t)(nrow * 64 + kbyte));
                LDM4(bhf[nt2 * 2][0], bhf[nt2 * 2][1], bhf[nt2 * 2 + 1][0], bhf[nt2 * 2 + 1][1], bb + 16384u + off);
            }
            #pragma unroll
            for (int mt = 0; mt < 4; mt++) {
                int mrow = warp_m * 64 + mt * 16 + (lane & 15);
                int kbyte = k16 * 32 + (lane >> 4) * 16;
                uint32_t off = SWZ32((uint32_t)(mrow * 64 + kbyte));
                LDM4(ah[mt][0], ah[mt][1], ah[mt][2], ah[mt][3], bb + off);
            }
            if (PASSES == 3) {
                uint32_t blf[4][2], al[4][4];
                #pragma unroll
                for (int nt2 = 0; nt2 < 2; nt2++) {
                    int nrow = warp_n * 32 + nt2 * 16 + (lane & 7) + ((lane & 16) ? 8 : 0);
                    int kbyte = k16 * 32 + ((lane >> 3) & 1) * 16;
                    uint32_t off = SWZ32((uint32_t)(nrow * 64 + kbyte));
                    LDM4(blf[nt2 * 2][0], blf[nt2 * 2][1], blf[nt2 * 2 + 1][0], blf[nt2 * 2 + 1][1], bb + 24576u + off);
                }
                #pragma unroll
                for (int mt = 0; mt < 4; mt++)
                    #pragma unroll
                    for (int nt = 0; nt < 4; nt++) MMA_F16(acc[mt][nt], ah[mt], bhf[nt]);
                #pragma unroll
                for (int mt = 0; mt < 4; mt++) {
                    int mrow = warp_m * 64 + mt * 16 + (lane & 15);
                    int kbyte = k16 * 32 + (lane >> 4) * 16;
                    uint32_t off = SWZ32((uint32_t)(mrow * 64 + kbyte));
                    LDM4(al[mt][0], al[mt][1], al[mt][2], al[mt][3], bb + 8192u + off);
                }
                #pragma unroll
                for (int mt = 0; mt < 4; mt++)
                    #pragma unroll
                    for (int nt = 0; nt < 4; nt++) MMA_F16(acc[mt][nt], ah[mt], blf[nt]);
                #pragma unroll
                for (int mt = 0; mt < 4; mt++)
                    #pragma unroll
                    for (int nt = 0; nt < 4; nt++) MMA_F16(acc[mt][nt], al[mt], bhf[nt]);
            } else {
                #pragma unroll
                for (int mt = 0; mt < 4; mt++)
                    #pragma unroll
                    for (int nt = 0; nt < 4; nt++) MMA_F16(acc[mt][nt], ah[mt], bhf[nt]);
            }
        }
    }

    const int g = lane >> 2, tg = lane & 3;
    #pragma unroll
    for (int mt = 0; mt < 4; mt++) {
        #pragma unroll
        for (int h8 = 0; h8 < 2; h8++) {
            int row = row0 + warp_m * 64 + mt * 16 + g + h8 * 8;
            #pragma unroll
            for (int nt = 0; nt < 4; nt++) {
                int colg = col0 + warp_n * 32 + nt * 8 + tg * 2;
                float2 o2 = make_float2(acc[mt][nt][h8 * 2 + 0] + aux[colg],
                                        acc[mt][nt][h8 * 2 + 1] + aux[colg + 1]);
                *(float2*)&out[(size_t)row * D + colg] = o2;
            }
        }
    }
    #undef MISSUE
}

// -------------------- flag: compact near-tie rows --------------------
__global__ void flag_kernel(const ull* __restrict__ b1, const ull* __restrict__ b2,
                            int* __restrict__ idx, int* __restrict__ list, int* __restrict__ cnt) {
    int r = blockIdx.x * blockDim.x + threadIdx.x;
    if (r >= NROWS) return;
    ull p1 = b1[r];
    idx[r] = (int)(p1 & 0xffffffffu);
    g_ex[r] = ~0ull;
    if (unpackd(b2[r]) - unpackd(p1) <= THRESH) {
        int pos = atomicAdd(cnt, 1);
        list[pos] = r;
    }
}

// -------------------- exact re-decide, tile-pruned --------------------
__global__ void exact_kernel(const float* __restrict__ x, int ldx,
                             const float* __restrict__ emb, int ntiles,
                             const float* __restrict__ nsq, const float* __restrict__ xnsq,
                             const int* __restrict__ list, const int* __restrict__ cnt,
                             const ull* __restrict__ b1, const ull* __restrict__ tilemin,
                             ull* __restrict__ ex) {
    int i = blockIdx.x;
    if (i >= *cnt) return;
    int r = list[i];
    __shared__ float xs[D];
    __shared__ ull wmin[8];
    const int t = threadIdx.x, lane = t & 31, w = t >> 5;
    if (t < 128) ((float4*)xs)[t] = *(const float4*)(x + (size_t)r * ldx + t * 4);
    if (t < 8) wmin[t] = ~0ull;
    __syncthreads();
    float xx = xnsq[r];
    float dcut = unpackd(b1[r]) + 2.f * THRESH;
    ull m = ~0ull;
    for (int tt = 0; tt < ntiles; tt++) {
        if (unpackd(tilemin[(size_t)r * MAXTILES + tt]) > dcut) continue;
        for (int cc = w; cc < BN; cc += 8) {
            int j = tt * BN + cc;
            const float* e = emb + (size_t)j * D;
            float s = 0.f;
            for (int k = lane; k < D; k += 32) s = fmaf(e[k], xs[k], s);
            #pragma unroll
            for (int o = 16; o; o >>= 1) s += __shfl_xor_sync(0xffffffffu, s, o);
            if (lane == 0) {
                float d = __fadd_rn(__fadd_rn(xx, nsq[j]), -2.f * s);
                ull p = packdi(d, (unsigned)j);
                if (p < m) m = p;
            }
        }
    }
    if (lane == 0) wmin[w] = m;
    __syncthreads();
    if (t == 0) {
        ull mm = wmin[0];
        #pragma unroll
        for (int k = 1; k < 8; k++) if (wmin[k] < mm) mm = wmin[k];
        ex[r] = mm;
    }
}

// -------------------- select exact winners --------------------
__global__ void sel_kernel(const int* __restrict__ list, const int* __restrict__ cnt,
                           const ull* __restrict__ ex, int* __restrict__ idx) {
    int i = blockIdx.x * blockDim.x + threadIdx.x;
    if (i < *cnt) { int r = list[i]; idx[r] = (int)(ex[r] & 0xffffffffu); }
}

// -------------------- gather q = emb[idx] (+ optional split), loss --------------------
__global__ void gather_loss(const float* __restrict__ emb, const int* __restrict__ idx,
                            const float* __restrict__ x, int ldx, float* __restrict__ q,
                            __half* __restrict__ qh, __half* __restrict__ ql) {
    int r = blockIdx.x;
    int j = idx[r];
    const float* e = emb + (size_t)j * D;
    const float* xr = x + (size_t)r * ldx;
    float* qr = q + (size_t)r * D;
    float ls = 0.f;
    for (int k = threadIdx.x; k < D; k += blockDim.x) {
        float ev = e[k];
        qr[k] = ev;
        __half hh = __float2half_rn(ev);
        qh[(size_t)r * D + k] = hh;
        if (ql) ql[(size_t)r * D + k] = __float2half_rn(ev - __half2float(hh));
        float dd = ev - xr[k];
        ls += dd * dd;
    }
    #pragma unroll
    for (int o = 16; o; o >>= 1) ls += __shfl_xor_sync(0xffffffffu, ls, o);
    __shared__ float ws[8];
    int w = threadIdx.x >> 5;
    if ((threadIdx.x & 31) == 0) ws[w] = ls;
    __syncthreads();
    if (threadIdx.x == 0) {
        float s = 0.f;
        for (int i = 0; i < 8; i++) s += ws[i];
        atomicAdd(&g_loss, s);
    }
}

// -------------------- LayerNorm + leakyReLU + fused follow-up --------------------
template <int MODE>
__global__ void ln_kernel(const float* __restrict__ h,
                          const float* __restrict__ g, const float* __restrict__ be,
                          const float* __restrict__ z,
                          const float* __restrict__ gc_raw, const float* __restrict__ gf_raw,
                          float* __restrict__ out)
{
    int r = blockIdx.x;
    int j = threadIdx.x;
    float hv = h[(size_t)r * D + j];
    float s = hv, sq = hv * hv;
    #pragma unroll
    for (int o = 16; o; o >>= 1) {
        s += __shfl_xor_sync(0xffffffffu, s, o);
        sq += __shfl_xor_sync(0xffffffffu, sq, o);
    }
    __shared__ float s1[16], s2[16];
    int w = j >> 5, lane = j & 31;
    if (lane == 0) { s1[w] = s; s2[w] = sq; }
    __syncthreads();
    if (w == 0) {
        s = (lane < 16) ? s1[lane] : 0.f;
        sq = (lane < 16) ? s2[lane] : 0.f;
        #pragma unroll
        for (int o = 8; o; o >>= 1) {
            s += __shfl_xor_sync(0xffffffffu, s, o);
            sq += __shfl_xor_sync(0xffffffffu, sq, o);
        }
        if (lane == 0) { s1[0] = s; s2[0] = sq; }
    }
    __syncthreads();
    float mean = s1[0] * (1.f / D);
    float var = s2[0] * (1.f / D) - mean * mean;
    float y = (hv - mean) * rsqrtf(var + 1e-5f) * g[j] + be[j];
    float act = y > 0.f ? y : 0.1f * y;
    float gcv = 1.f / (1.f + expf(-gc_raw[0]));

    if (MODE == 0) {
        float rv = z[(size_t)r * 1024 + D + j] - gcv * act;
        g_ci[(size_t)r * D + j] = act;
        g_res[(size_t)r * D + j] = rv;
        g_res_h[(size_t)r * D + j] = __float2half_rn(rv);
        float rq = rv * rv;
        #pragma unroll
        for (int o = 16; o; o >>= 1) rq += __shfl_xor_sync(0xffffffffu, rq, o);
        __syncthreads();
        if (lane == 0) s1[w] = rq;
        __syncthreads();
        if (j == 0) {
            float tt = 0.f;
            #pragma unroll
            for (int i = 0; i < 16; i++) tt += s1[i];
            g_xnsq_f[r] = tt;
        }
    } else {
        float gfv = 1.f / (1.f + expf(-gf_raw[0]));
        out[(size_t)r * 1024 + j] = g_qc[(size_t)r * D + j] + 0.1f * gfv * act;
        out[(size_t)r * 1024 + D + j] = g_qf[(size_t)r * D + j] + gcv * g_ci[(size_t)r * D + j];
        if (r == 0 && j == 0)
            out[(size_t)NROWS * 1024] = 1.25f * g_loss / (float)((size_t)NROWS * D);
    }
}

// -------------------- launch --------------------
#define SYMADDR(p, s) cudaGetSymbolAddress((void**)&p, s)

extern "C" void kernel_launch(void* const* d_in, const int* in_sizes, int n_in,
                              void* d_out, int out_size) {
    const float* z      = (const float*)d_in[0];
    const float* ce     = (const float*)d_in[1];
    const float* fe     = (const float*)d_in[2];
    const float* w_c2f  = (const float*)d_in[3];
    const float* b_c2f  = (const float*)d_in[4];
    const float* g_c2f  = (const float*)d_in[5];
    const float* be_c2f = (const float*)d_in[6];
    const float* w_f2c  = (const float*)d_in[7];
    const float* b_f2c  = (const float*)d_in[8];
    const float* g_f2c  = (const float*)d_in[9];
    const float* be_f2c = (const float*)d_in[10];
    const float* gc_raw = (const float*)d_in[11];
    const float* gf_raw = (const float*)d_in[12];
    float* out = (float*)d_out;

    float *nsq_c, *nsq_f, *xnsq_c, *xnsq_f, *qc, *qf, *res, *h;
    ull *b1c, *b2c, *b1f, *b2f, *ex, *tmin;
    int *idx_c, *idx_f, *list, *cnt_c, *cnt_f;
    __half *zc_h, *ce_h, *fe_h, *res_h, *q_h, *q_l;
    __half *w1_h, *w1_l, *w2_h, *w2_l;
    SYMADDR(nsq_c, g_nsq_c);   SYMADDR(nsq_f, g_nsq_f);
    SYMADDR(xnsq_c, g_xnsq_c); SYMADDR(xnsq_f, g_xnsq_f);
    SYMADDR(b1c, g_b1c); SYMADDR(b2c, g_b2c); SYMADDR(b1f, g_b1f); SYMADDR(b2f, g_b2f);
    SYMADDR(ex, g_ex); SYMADDR(tmin, g_tmin);
    SYMADDR(idx_c, g_idx_c); SYMADDR(idx_f, g_idx_f);
    SYMADDR(list, g_list);
    SYMADDR(cnt_c, g_cnt_c); SYMADDR(cnt_f, g_cnt_f);
    SYMADDR(qc, g_qc); SYMADDR(qf, g_qf); SYMADDR(res, g_res); SYMADDR(h, g_h);
    SYMADDR(zc_h, g_zc_h);
    SYMADDR(ce_h, g_ce_h);
    SYMADDR(fe_h, g_fe_h);
    SYMADDR(res_h, g_res_h);
    SYMADDR(q_h, g_q_h); SYMADDR(q_l, g_q_l);
    SYMADDR(w1_h, g_w1_h); SYMADDR(w1_l, g_w1_l);
    SYMADDR(w2_h, g_w2_h); SYMADDR(w2_l, g_w2_l);

    cudaFuncSetAttribute(vq_gemm, cudaFuncAttributeMaxDynamicSharedMemorySize, SMEM_DYN);
    cudaFuncSetAttribute(mlp_gemm<3>, cudaFuncAttributeMaxDynamicSharedMemorySize, SMEM_DYN);
    cudaFuncSetAttribute(mlp_gemm<1>, cudaFuncAttributeMaxDynamicSharedMemorySize, SMEM_DYN);

    init_kernel<<<NROWS / 256, 256>>>();
    {
        int warps = CB + FB + NROWS + 2 * D;
        prep_split<<<(warps * 32 + 255) / 256, 256>>>(z, ce, fe, w_c2f, w_f2c);
    }
    // coarse VQ
    vq_gemm<<<dim3(NROWS / BM, CB / BN), 256, SMEM_DYN>>>(zc_h, ce_h, nsq_c, xnsq_c, b1c, b2c, tmin);
    flag_kernel<<<NROWS / 256, 256>>>(b1c, b2c, idx_c, list, cnt_c);
    exact_kernel<<<NROWS, 256>>>(z, 1024, ce, CB / BN, nsq_c, xnsq_c, list, cnt_c, b1c, tmin, ex);
    sel_kernel<<<NROWS / 256, 256>>>(list, cnt_c, ex, idx_c);
    gather_loss<<<NROWS, 256>>>(ce, idx_c, z, 1024, qc, q_h, q_l);
    // MLP c2f (3-pass: res precision is argmin-critical downstream)
    mlp_gemm<3><<<dim3(NROWS / BM, D / BN), 256, SMEM_DYN>>>(q_h, q_l, w1_h, w1_l, b_c2f, h);
    ln_kernel<0><<<NROWS, 512>>>(h, g_c2f, be_c2f, z, gc_raw, gf_raw, nullptr);
    // fine VQ
    vq_gemm<<<dim3(NROWS / BM, FB / BN), 256, SMEM_DYN>>>(res_h, fe_h, nsq_f, xnsq_f, b1f, b2f, tmin);
    flag_kernel<<<NROWS / 256, 256>>>(b1f, b2f, idx_f, list, cnt_f);
    exact_kernel<<<NROWS, 256>>>(res, D, fe, FB / BN, nsq_f, xnsq_f, list, cnt_f, b1f, tmin, ex);
    sel_kernel<<<NROWS / 256, 256>>>(list, cnt_f, ex, idx_f);
    gather_loss<<<NROWS, 256>>>(fe, idx_f, res, D, qf, q_h, nullptr);
    // MLP f2c (1-pass: output contribution scaled by 0.1*gf, error ~1e-5)
    mlp_gemm<1><<<dim3(NROWS / BM, D / BN), 256, SMEM_DYN>>>(q_h, nullptr, w2_h, nullptr, b_f2c, h);
    ln_kernel<1><<<NROWS, 512>>>(h, g_f2c, be_f2c, z, gc_raw, gf_raw, out);
}

// round 17
// speedup vs baseline: 1.3015x; 1.0532x over previous
#include <cuda_runtime.h>
#include <cuda_fp16.h>
#include <cstdint>
#include <math.h>

#define NROWS 8192
#define D     512
#define CB    4096
#define FB    8192
#define BM    128
#define BN    128
#define KC    32
#define NCH   (D / KC)
#define VKC   64
#define VNCH  (D / VKC)
#define THRESH 4e-3f
#define SMEM_DYN 98304
#define MAXTILES 64

typedef unsigned long long ull;

// -------------------- device scratch --------------------
__device__ float g_nsq_c[CB], g_nsq_f[FB];
__device__ float g_xnsq_c[NROWS], g_xnsq_f[NROWS];
__device__ ull   g_b1c[NROWS], g_b2c[NROWS], g_b1f[NROWS], g_b2f[NROWS];
__device__ ull   g_ex[NROWS];
__device__ ull   g_tmin[NROWS * MAXTILES];
__device__ int   g_list[NROWS];
__device__ int   g_cnt_c, g_cnt_f;
__device__ float g_qc[NROWS * D], g_qf[NROWS * D];
__device__ float g_ci[NROWS * D], g_res[NROWS * D], g_h[NROWS * D];
__device__ __half g_zc_h[NROWS * D];
__device__ __half g_ce_h[CB * D];
__device__ __half g_fe_h[FB * D];
__device__ __half g_res_h[NROWS * D];
__device__ __half g_q_h[NROWS * D], g_q_l[NROWS * D];
__device__ __half g_w1_h[D * D], g_w1_l[D * D], g_w2_h[D * D], g_w2_l[D * D];
__device__ float g_loss;

// -------------------- helpers --------------------
__device__ __forceinline__ uint32_t smem_u32(const void* p) {
    uint32_t a;
    asm("{ .reg .u64 t; cvta.to.shared.u64 t, %1; cvt.u32.u64 %0, t; }" : "=r"(a) : "l"(p));
    return a;
}
#define SWZ32(o)  ((o) ^ (((o) >> 3) & 0x30))   // 64B rows
#define SWZ128(o) ((o) ^ (((o) >> 3) & 0x70))   // 128B rows
#define LDM4(r0, r1, r2, r3, a) \
    asm volatile("ldmatrix.sync.aligned.m8n8.x4.shared.b16 {%0,%1,%2,%3}, [%4];" \
        : "=r"(r0), "=r"(r1), "=r"(r2), "=r"(r3) : "r"(a))
#define MMA_F16(c, a, b) \
    asm volatile("mma.sync.aligned.m16n8k16.row.col.f32.f16.f16.f32 " \
        "{%0,%1,%2,%3}, {%4,%5,%6,%7}, {%8,%9}, {%0,%1,%2,%3};" \
        : "+f"((c)[0]), "+f"((c)[1]), "+f"((c)[2]), "+f"((c)[3]) \
        : "r"((a)[0]), "r"((a)[1]), "r"((a)[2]), "r"((a)[3]), "r"((b)[0]), "r"((b)[1]))
#define CP_ASYNC16(dst, src) \
    asm volatile("cp.async.cg.shared.global [%0], [%1], 16;" :: "r"(dst), "l"(src))
#define CP_COMMIT() asm volatile("cp.async.commit_group;")
#define CP_WAIT1()  asm volatile("cp.async.wait_group 1;")

__device__ __forceinline__ ull packdi(float d, unsigned j) {
    unsigned u = __float_as_uint(d);
    u = (u & 0x80000000u) ? ~u : (u | 0x80000000u);
    return ((ull)u << 32) | (ull)j;
}
__device__ __forceinline__ float unpackd(ull p) {
    unsigned u = (unsigned)(p >> 32);
    u = (u & 0x80000000u) ? (u & 0x7fffffffu) : ~u;
    return __uint_as_float(u);
}
__device__ __forceinline__ void top2ins(ull& m1, ull& m2, ull p) {
    if (p < m1) { m2 = m1; m1 = p; }
    else if (p < m2) m2 = p;
}

// -------------------- launch 1: init --------------------
__global__ void init_kernel() {
    int r = blockIdx.x * blockDim.x + threadIdx.x;
    if (r < NROWS) {
        g_b1c[r] = ~0ull; g_b2c[r] = ~0ull;
        g_b1f[r] = ~0ull; g_b2f[r] = ~0ull;
    }
    if (r == 0) { g_loss = 0.f; g_cnt_c = 0; g_cnt_f = 0; }
}

// -------------------- launch 2: fused norms + fp16 splits --------------------
__global__ void prep_split(const float* __restrict__ z,
                           const float* __restrict__ ce, const float* __restrict__ fe,
                           const float* __restrict__ w1, const float* __restrict__ w2) {
    int gw = (blockIdx.x * blockDim.x + threadIdx.x) >> 5;
    int lane = threadIdx.x & 31;
    const float* src;
    __half *hi, *lo = nullptr;
    float* nrm = nullptr;
    if (gw < CB) {
        src = ce + (size_t)gw * D; hi = g_ce_h + (size_t)gw * D; nrm = g_nsq_c + gw;
    } else if (gw < CB + FB) {
        int r = gw - CB;
        src = fe + (size_t)r * D; hi = g_fe_h + (size_t)r * D; nrm = g_nsq_f + r;
    } else if (gw < CB + FB + NROWS) {
        int r = gw - CB - FB;
        src = z + (size_t)r * 1024; hi = g_zc_h + (size_t)r * D; nrm = g_xnsq_c + r;
    } else if (gw < CB + FB + NROWS + D) {
        int r = gw - CB - FB - NROWS;
        src = w1 + (size_t)r * D; hi = g_w1_h + (size_t)r * D; lo = g_w1_l + (size_t)r * D;
    } else if (gw < CB + FB + NROWS + 2 * D) {
        int r = gw - CB - FB - NROWS - D;
        src = w2 + (size_t)r * D; hi = g_w2_h + (size_t)r * D; lo = g_w2_l + (size_t)r * D;
    } else return;

    float s = 0.f;
    #pragma unroll
    for (int it = 0; it < 4; it++) {
        int c = lane * 4 + it * 128;
        float4 v = *(const float4*)(src + c);
        s += v.x * v.x + v.y * v.y + v.z * v.z + v.w * v.w;
        __half hs[4];
        hs[0] = __float2half_rn(v.x); hs[1] = __float2half_rn(v.y);
        hs[2] = __float2half_rn(v.z); hs[3] = __float2half_rn(v.w);
        *(uint2*)(hi + c) = *(uint2*)hs;
        if (lo) {
            __half ls[4];
            ls[0] = __float2half_rn(v.x - __half2float(hs[0]));
            ls[1] = __float2half_rn(v.y - __half2float(hs[1]));
            ls[2] = __float2half_rn(v.z - __half2float(hs[2]));
            ls[3] = __float2half_rn(v.w - __half2float(hs[3]));
            *(uint2*)(lo + c) = *(uint2*)ls;
        }
    }
    if (nrm) {
        #pragma unroll
        for (int o = 16; o; o >>= 1) s += __shfl_xor_sync(0xffffffffu, s, o);
        if (lane == 0) *nrm = s;
    }
}

// -------------------- VQ GEMM: 256 thr, 128x128, KC=64, 1-pass hh, fully unrolled --------------------
__global__ __launch_bounds__(256, 2) void vq_gemm(
    const __half* __restrict__ Ah, const __half* __restrict__ Bh,
    const float* __restrict__ aux, const float* __restrict__ xnsq,
    ull* __restrict__ best1, ull* __restrict__ best2,
    ull* __restrict__ tilemin)
{
    extern __shared__ char sm[];
    __shared__ ull sb1[BM], sb2[BM];
    const int t = threadIdx.x;
    const int lane = t & 31, wid = t >> 5;
    const int warp_m = wid & 1, warp_n = wid >> 1;
    const int row0 = blockIdx.x * BM, col0 = blockIdx.y * BN;
    const uint32_t smb = smem_u32(sm);

    if (t < BM) { sb1[t] = ~0ull; sb2[t] = ~0ull; }

    float acc[4][4][4];
    #pragma unroll
    for (int i = 0; i < 4; i++)
        #pragma unroll
        for (int j = 0; j < 4; j++)
            #pragma unroll
            for (int k = 0; k < 4; k++) acc[i][j][k] = 0.f;

    const int lr = t >> 1, lsg = t & 1;
    const size_t aoff = (size_t)(row0 + lr) * D + lsg * 32;
    const size_t boff = (size_t)(col0 + lr) * D + lsg * 32;
    const uint32_t s0 = SWZ128((uint32_t)(lr * 128 + lsg * 64));
    const uint32_t s1 = SWZ128((uint32_t)(lr * 128 + lsg * 64 + 16));
    const uint32_t s2 = SWZ128((uint32_t)(lr * 128 + lsg * 64 + 32));
    const uint32_t s3 = SWZ128((uint32_t)(lr * 128 + lsg * 64 + 48));

    #define VISSUE(c) do { \
        uint32_t bb = smb + (uint32_t)((c) % 3) * 32768u; \
        const int kb = (c) * VKC; \
        CP_ASYNC16(bb + s0, (const char*)(Ah + aoff + kb)); \
        CP_ASYNC16(bb + s1, (const char*)(Ah + aoff + kb + 8)); \
        CP_ASYNC16(bb + s2, (const char*)(Ah + aoff + kb + 16)); \
        CP_ASYNC16(bb + s3, (const char*)(Ah + aoff + kb + 24)); \
        CP_ASYNC16(bb + 16384u + s0, (const char*)(Bh + boff + kb)); \
        CP_ASYNC16(bb + 16384u + s1, (const char*)(Bh + boff + kb + 8)); \
        CP_ASYNC16(bb + 16384u + s2, (const char*)(Bh + boff + kb + 16)); \
        CP_ASYNC16(bb + 16384u + s3, (const char*)(Bh + boff + kb + 24)); \
        CP_COMMIT(); \
    } while (0)

    VISSUE(0);
    VISSUE(1);

    #pragma unroll
    for (int c = 0; c < VNCH; c++) {
        const uint32_t bb = smb + (uint32_t)(c % 3) * 32768u;
        CP_WAIT1();
        __syncthreads();
        if (c + 2 < VNCH) VISSUE(c + 2);
        #pragma unroll
        for (int k16 = 0; k16 < 4; k16++) {
            uint32_t bhf[4][2], ah[4][4];
            #pragma unroll
            for (int nt2 = 0; nt2 < 2; nt2++) {
                int nrow = warp_n * 32 + nt2 * 16 + (lane & 7) + ((lane & 16) ? 8 : 0);
                int kbyte = k16 * 32 + ((lane >> 3) & 1) * 16;
                uint32_t off = SWZ128((uint32_t)(nrow * 128 + kbyte));
                LDM4(bhf[nt2 * 2][0], bhf[nt2 * 2][1], bhf[nt2 * 2 + 1][0], bhf[nt2 * 2 + 1][1],
                     bb + 16384u + off);
            }
            #pragma unroll
            for (int mt = 0; mt < 4; mt++) {
                int mrow = warp_m * 64 + mt * 16 + (lane & 15);
                int kbyte = k16 * 32 + (lane >> 4) * 16;
                uint32_t off = SWZ128((uint32_t)(mrow * 128 + kbyte));
                LDM4(ah[mt][0], ah[mt][1], ah[mt][2], ah[mt][3], bb + off);
            }
            #pragma unroll
            for (int mt = 0; mt < 4; mt++)
                #pragma unroll
                for (int nt = 0; nt < 4; nt++) MMA_F16(acc[mt][nt], ah[mt], bhf[nt]);
        }
    }

    const int g = lane >> 2, tg = lane & 3;
    #pragma unroll
    for (int mt = 0; mt < 4; mt++) {
        #pragma unroll
        for (int h8 = 0; h8 < 2; h8++) {
            int lrow2 = warp_m * 64 + mt * 16 + g + h8 * 8;
            float xx = xnsq[row0 + lrow2];
            ull m1 = ~0ull, m2 = ~0ull;
            #pragma unroll
            for (int nt = 0; nt < 4; nt++) {
                int colg = col0 + warp_n * 32 + nt * 8 + tg * 2;
                float d0 = __fadd_rn(__fadd_rn(xx, aux[colg]), -2.f * acc[mt][nt][h8 * 2 + 0]);
                float d1 = __fadd_rn(__fadd_rn(xx, aux[colg + 1]), -2.f * acc[mt][nt][h8 * 2 + 1]);
                top2ins(m1, m2, packdi(d0, (unsigned)colg));
                top2ins(m1, m2, packdi(d1, (unsigned)(colg + 1)));
            }
            #pragma unroll
            for (int o = 1; o <= 2; o <<= 1) {
                ull o1 = __shfl_xor_sync(0xffffffffu, m1, o);
                ull o2 = __shfl_xor_sync(0xffffffffu, m2, o);
                ull n1 = o1 < m1 ? o1 : m1;
                ull hi = o1 > m1 ? o1 : m1;
                ull lo2 = o2 < m2 ? o2 : m2;
                m2 = hi < lo2 ? hi : lo2;
                m1 = n1;
            }
            if (tg == 0) {
                ull old = atomicMin(&sb1[lrow2], m1);
                atomicMin(&sb2[lrow2], old > m1 ? old : m1);
                atomicMin(&sb2[lrow2], m2);
            }
        }
    }
    __syncthreads();
    if (t < BM) {
        ull v1 = sb1[t], v2 = sb2[t];
        ull old = atomicMin(&best1[row0 + t], v1);
        atomicMin(&best2[row0 + t], old > v1 ? old : v1);
        atomicMin(&best2[row0 + t], v2);
        tilemin[(size_t)(row0 + t) * MAXTILES + blockIdx.y] = v1;
    }
    #undef VISSUE
}

// -------------------- MLP GEMM: PASSES=3 (c2f) or 1 (f2c) --------------------
template <int PASSES>
__global__ __launch_bounds__(256, 2) void mlp_gemm(
    const __half* __restrict__ Ah, const __half* __restrict__ Al,
    const __half* __restrict__ Bh, const __half* __restrict__ Bl,
    const float* __restrict__ aux, float* __restrict__ out)
{
    extern __shared__ char sm[];
    const int t = threadIdx.x;
    const int lane = t & 31, wid = t >> 5;
    const int warp_m = wid & 1, warp_n = wid >> 1;
    const int row0 = blockIdx.x * BM, col0 = blockIdx.y * BN;
    const uint32_t smb = smem_u32(sm);

    float acc[4][4][4];
    #pragma unroll
    for (int i = 0; i < 4; i++)
        #pragma unroll
        for (int j = 0; j < 4; j++)
            #pragma unroll
            for (int k = 0; k < 4; k++) acc[i][j][k] = 0.f;

    const int lrow = t >> 1, lh = t & 1;
    const size_t aoff = (size_t)(row0 + lrow) * D + lh * 16;
    const size_t boff = (size_t)(col0 + lrow) * D + lh * 16;
    const uint32_t st0 = SWZ32((uint32_t)(lrow * 64 + lh * 32));
    const uint32_t st1 = SWZ32((uint32_t)(lrow * 64 + lh * 32 + 16));

    #define MISSUE(c) do { \
        uint32_t bb = smb + (uint32_t)((c) % 3) * 32768u; \
        const int kb = (c) * KC; \
        CP_ASYNC16(bb + st0, (const char*)(Ah + aoff + kb)); \
        CP_ASYNC16(bb + st1, (const char*)(Ah + aoff + kb + 8)); \
        CP_ASYNC16(bb + 16384u + st0, (const char*)(Bh + boff + kb)); \
        CP_ASYNC16(bb + 16384u + st1, (const char*)(Bh + boff + kb + 8)); \
        if (PASSES == 3) { \
            CP_ASYNC16(bb + 8192u  + st0, (const char*)(Al + aoff + kb)); \
            CP_ASYNC16(bb + 8192u  + st1, (const char*)(Al + aoff + kb + 8)); \
            CP_ASYNC16(bb + 24576u + st0, (const char*)(Bl + boff + kb)); \
            CP_ASYNC16(bb + 24576u + st1, (const char*)(Bl + boff + kb + 8)); \
        } \
        CP_COMMIT(); \
    } while (0)

    MISSUE(0);
    MISSUE(1);

    #pragma unroll 1
    for (int c = 0; c < NCH; c++) {
        const uint32_t bb = smb + (uint32_t)(c % 3) * 32768u;
        CP_WAIT1();
        __syncthreads();
        if (c + 2 < NCH) MISSUE(c + 2);
        #pragma unroll
        for (int k16 = 0; k16 < 2; k16++) {
            uint32_t bhf[4][2], ah[4][4];
            #pragma unroll
            for (int nt2 = 0; nt2 < 2; nt2++) {
                int nrow = warp_n * 32 + nt2 * 16 + (lane & 7) + ((lane & 16) ? 8 : 0);
                int kbyte = k16 * 32 + ((lane >> 3) & 1) * 16;
                uint32_t off = SWZ32((uint32_t)(nrow * 64 + kbyte));
                LDM4(bhf[nt2 * 2][0], bhf[nt2 * 2][1], bhf[nt2 * 2 + 1][0], bhf[nt2 * 2 + 1][1], bb + 16384u + off);
            }
            #pragma unroll
            for (int mt = 0; mt < 4; mt++) {
                int mrow = warp_m * 64 + mt * 16 + (lane & 15);
                int kbyte = k16 * 32 + (lane >> 4) * 16;
                uint32_t off = SWZ32((uint32_t)(mrow * 64 + kbyte));
                LDM4(ah[mt][0], ah[mt][1], ah[mt][2], ah[mt][3], bb + off);
            }
            if (PASSES == 3) {
                uint32_t blf[4][2], al[4][4];
                #pragma unroll
                for (int nt2 = 0; nt2 < 2; nt2++) {
                    int nrow = warp_n * 32 + nt2 * 16 + (lane & 7) + ((lane & 16) ? 8 : 0);
                    int kbyte = k16 * 32 + ((lane >> 3) & 1) * 16;
                    uint32_t off = SWZ32((uint32_t)(nrow * 64 + kbyte));
                    LDM4(blf[nt2 * 2][0], blf[nt2 * 2][1], blf[nt2 * 2 + 1][0], blf[nt2 * 2 + 1][1], bb + 24576u + off);
                }
                #pragma unroll
                for (int mt = 0; mt < 4; mt++)
                    #pragma unroll
                    for (int nt = 0; nt < 4; nt++) MMA_F16(acc[mt][nt], ah[mt], bhf[nt]);
                #pragma unroll
                for (int mt = 0; mt < 4; mt++) {
                    int mrow = warp_m * 64 + mt * 16 + (lane & 15);
                    int kbyte = k16 * 32 + (lane >> 4) * 16;
                    uint32_t off = SWZ32((uint32_t)(mrow * 64 + kbyte));
                    LDM4(al[mt][0], al[mt][1], al[mt][2], al[mt][3], bb + 8192u + off);
                }
                #pragma unroll
                for (int mt = 0; mt < 4; mt++)
                    #pragma unroll
                    for (int nt = 0; nt < 4; nt++) MMA_F16(acc[mt][nt], ah[mt], blf[nt]);
                #pragma unroll
                for (int mt = 0; mt < 4; mt++)
                    #pragma unroll
                    for (int nt = 0; nt < 4; nt++) MMA_F16(acc[mt][nt], al[mt], bhf[nt]);
            } else {
                #pragma unroll
                for (int mt = 0; mt < 4; mt++)
                    #pragma unroll
                    for (int nt = 0; nt < 4; nt++) MMA_F16(acc[mt][nt], ah[mt], bhf[nt]);
            }
        }
    }

    const int g = lane >> 2, tg = lane & 3;
    #pragma unroll
    for (int mt = 0; mt < 4; mt++) {
        #pragma unroll
        for (int h8 = 0; h8 < 2; h8++) {
            int row = row0 + warp_m * 64 + mt * 16 + g + h8 * 8;
            #pragma unroll
            for (int nt = 0; nt < 4; nt++) {
                int colg = col0 + warp_n * 32 + nt * 8 + tg * 2;
                float2 o2 = make_float2(acc[mt][nt][h8 * 2 + 0] + aux[colg],
                                        acc[mt][nt][h8 * 2 + 1] + aux[colg + 1]);
                *(float2*)&out[(size_t)row * D + colg] = o2;
            }
        }
    }
    #undef MISSUE
}

// -------------------- flag: compact near-tie rows (list only) --------------------
__global__ void flag_kernel(const ull* __restrict__ b1, const ull* __restrict__ b2,
                            int* __restrict__ list, int* __restrict__ cnt) {
    int r = blockIdx.x * blockDim.x + threadIdx.x;
    if (r >= NROWS) return;
    g_ex[r] = ~0ull;
    if (unpackd(b2[r]) - unpackd(b1[r]) <= THRESH) {
        int pos = atomicAdd(cnt, 1);
        list[pos] = r;
    }
}

// -------------------- exact re-decide, tile-pruned, strided blocks --------------------
__global__ void exact_kernel(const float* __restrict__ x, int ldx,
                             const float* __restrict__ emb, int ntiles,
                             const float* __restrict__ nsq, const float* __restrict__ xnsq,
                             const int* __restrict__ list, const int* __restrict__ cnt,
                             const ull* __restrict__ b1, const ull* __restrict__ tilemin,
                             ull* __restrict__ ex) {
    __shared__ float xs[D];
    __shared__ ull wmin[8];
    const int t = threadIdx.x, lane = t & 31, w = t >> 5;
    int n = *cnt;
    for (int i = blockIdx.x; i < n; i += gridDim.x) {
        int r = list[i];
        __syncthreads();
        if (t < 128) ((float4*)xs)[t] = *(const float4*)(x + (size_t)r * ldx + t * 4);
        if (t < 8) wmin[t] = ~0ull;
        __syncthreads();
        float xx = xnsq[r];
        float dcut = unpackd(b1[r]) + 2.f * THRESH;
        ull m = ~0ull;
        for (int tt = 0; tt < ntiles; tt++) {
            if (unpackd(tilemin[(size_t)r * MAXTILES + tt]) > dcut) continue;
            for (int cc = w; cc < BN; cc += 8) {
                int j = tt * BN + cc;
                const float* e = emb + (size_t)j * D;
                float s = 0.f;
                for (int k = lane; k < D; k += 32) s = fmaf(e[k], xs[k], s);
                #pragma unroll
                for (int o = 16; o; o >>= 1) s += __shfl_xor_sync(0xffffffffu, s, o);
                if (lane == 0) {
                    float d = __fadd_rn(__fadd_rn(xx, nsq[j]), -2.f * s);
                    ull p = packdi(d, (unsigned)j);
                    if (p < m) m = p;
                }
            }
        }
        if (lane == 0) wmin[w] = m;
        __syncthreads();
        if (t == 0) {
            ull mm = wmin[0];
            #pragma unroll
            for (int k = 1; k < 8; k++) if (wmin[k] < mm) mm = wmin[k];
            ex[r] = mm;
        }
    }
}

// -------------------- gather q = emb[idx] (+ optional split), loss; decides idx inline --------------------
__global__ void gather_loss(const float* __restrict__ emb,
                            const ull* __restrict__ b1, const ull* __restrict__ b2,
                            const ull* __restrict__ ex,
                            const float* __restrict__ x, int ldx, float* __restrict__ q,
                            __half* __restrict__ qh, __half* __restrict__ ql) {
    int r = blockIdx.x;
    ull p1 = b1[r];
    int j = (unpackd(b2[r]) - unpackd(p1) <= THRESH) ? (int)(ex[r] & 0xffffffffu)
                                                     : (int)(p1 & 0xffffffffu);
    const float* e = emb + (size_t)j * D;
    const float* xr = x + (size_t)r * ldx;
    float* qr = q + (size_t)r * D;
    float lsum = 0.f;
    for (int k = threadIdx.x; k < D; k += blockDim.x) {
        float ev = e[k];
        qr[k] = ev;
        __half hh = __float2half_rn(ev);
        qh[(size_t)r * D + k] = hh;
        if (ql) ql[(size_t)r * D + k] = __float2half_rn(ev - __half2float(hh));
        float dd = ev - xr[k];
        lsum += dd * dd;
    }
    #pragma unroll
    for (int o = 16; o; o >>= 1) lsum += __shfl_xor_sync(0xffffffffu, lsum, o);
    __shared__ float ws[8];
    int w = threadIdx.x >> 5;
    if ((threadIdx.x & 31) == 0) ws[w] = lsum;
    __syncthreads();
    if (threadIdx.x == 0) {
        float s = 0.f;
        for (int i = 0; i < 8; i++) s += ws[i];
        atomicAdd(&g_loss, s);
    }
}

// -------------------- LayerNorm + leakyReLU + fused follow-up --------------------
template <int MODE>
__global__ void ln_kernel(const float* __restrict__ h,
                          const float* __restrict__ g, const float* __restrict__ be,
                          const float* __restrict__ z,
                          const float* __restrict__ gc_raw, const float* __restrict__ gf_raw,
                          float* __restrict__ out)
{
    int r = blockIdx.x;
    int j = threadIdx.x;
    float hv = h[(size_t)r * D + j];
    float s = hv, sq = hv * hv;
    #pragma unroll
    for (int o = 16; o; o >>= 1) {
        s += __shfl_xor_sync(0xffffffffu, s, o);
        sq += __shfl_xor_sync(0xffffffffu, sq, o);
    }
    __shared__ float s1[16], s2[16];
    int w = j >> 5, lane = j & 31;
    if (lane == 0) { s1[w] = s; s2[w] = sq; }
    __syncthreads();
    if (w == 0) {
        s = (lane < 16) ? s1[lane] : 0.f;
        sq = (lane < 16) ? s2[lane] : 0.f;
        #pragma unroll
        for (int o = 8; o; o >>= 1) {
            s += __shfl_xor_sync(0xffffffffu, s, o);
            sq += __shfl_xor_sync(0xffffffffu, sq, o);
        }
        if (lane == 0) { s1[0] = s; s2[0] = sq; }
    }
    __syncthreads();
    float mean = s1[0] * (1.f / D);
    float var = s2[0] * (1.f / D) - mean * mean;
    float y = (hv - mean) * rsqrtf(var + 1e-5f) * g[j] + be[j];
    float act = y > 0.f ? y : 0.1f * y;
    float gcv = 1.f / (1.f + expf(-gc_raw[0]));

    if (MODE == 0) {
        float rv = z[(size_t)r * 1024 + D + j] - gcv * act;
        g_ci[(size_t)r * D + j] = act;
        g_res[(size_t)r * D + j] = rv;
        g_res_h[(size_t)r * D + j] = __float2half_rn(rv);
        float rq = rv * rv;
        #pragma unroll
        for (int o = 16; o; o >>= 1) rq += __shfl_xor_sync(0xffffffffu, rq, o);
        __syncthreads();
        if (lane == 0) s1[w] = rq;
        __syncthreads();
        if (j == 0) {
            float tt = 0.f;
            #pragma unroll
            for (int i = 0; i < 16; i++) tt += s1[i];
            g_xnsq_f[r] = tt;
        }
    } else {
        float gfv = 1.f / (1.f + expf(-gf_raw[0]));
        out[(size_t)r * 1024 + j] = g_qc[(size_t)r * D + j] + 0.1f * gfv * act;
        out[(size_t)r * 1024 + D + j] = g_qf[(size_t)r * D + j] + gcv * g_ci[(size_t)r * D + j];
        if (r == 0 && j == 0)
            out[(size_t)NROWS * 1024] = 1.25f * g_loss / (float)((size_t)NROWS * D);
    }
}

// -------------------- launch --------------------
#define SYMADDR(p, s) cudaGetSymbolAddress((void**)&p, s)

extern "C" void kernel_launch(void* const* d_in, const int* in_sizes, int n_in,
                              void* d_out, int out_size) {
    const float* z      = (const float*)d_in[0];
    const float* ce     = (const float*)d_in[1];
    const float* fe     = (const float*)d_in[2];
    const float* w_c2f  = (const float*)d_in[3];
    const float* b_c2f  = (const float*)d_in[4];
    const float* g_c2f  = (const float*)d_in[5];
    const float* be_c2f = (const float*)d_in[6];
    const float* w_f2c  = (const float*)d_in[7];
    const float* b_f2c  = (const float*)d_in[8];
    const float* g_f2c  = (const float*)d_in[9];
    const float* be_f2c = (const float*)d_in[10];
    const float* gc_raw = (const float*)d_in[11];
    const float* gf_raw = (const float*)d_in[12];
    float* out = (float*)d_out;

    float *nsq_c, *nsq_f, *xnsq_c, *xnsq_f, *qc, *qf, *res, *h;
    ull *b1c, *b2c, *b1f, *b2f, *ex, *tmin;
    int *list, *cnt_c, *cnt_f;
    __half *zc_h, *ce_h, *fe_h, *res_h, *q_h, *q_l;
    __half *w1_h, *w1_l, *w2_h, *w2_l;
    SYMADDR(nsq_c, g_nsq_c);   SYMADDR(nsq_f, g_nsq_f);
    SYMADDR(xnsq_c, g_xnsq_c); SYMADDR(xnsq_f, g_xnsq_f);
    SYMADDR(b1c, g_b1c); SYMADDR(b2c, g_b2c); SYMADDR(b1f, g_b1f); SYMADDR(b2f, g_b2f);
    SYMADDR(ex, g_ex); SYMADDR(tmin, g_tmin);
    SYMADDR(list, g_list);
    SYMADDR(cnt_c, g_cnt_c); SYMADDR(cnt_f, g_cnt_f);
    SYMADDR(qc, g_qc); SYMADDR(qf, g_qf); SYMADDR(res, g_res); SYMADDR(h, g_h);
    SYMADDR(zc_h, g_zc_h);
    SYMADDR(ce_h, g_ce_h);
    SYMADDR(fe_h, g_fe_h);
    SYMADDR(res_h, g_res_h);
    SYMADDR(q_h, g_q_h); SYMADDR(q_l, g_q_l);
    SYMADDR(w1_h, g_w1_h); SYMADDR(w1_l, g_w1_l);
    SYMADDR(w2_h, g_w2_h); SYMADDR(w2_l, g_w2_l);

    cudaFuncSetAttribute(vq_gemm, cudaFuncAttributeMaxDynamicSharedMemorySize, SMEM_DYN);
    cudaFuncSetAttribute(mlp_gemm<3>, cudaFuncAttributeMaxDynamicSharedMemorySize, SMEM_DYN);
    cudaFuncSetAttribute(mlp_gemm<1>, cudaFuncAttributeMaxDynamicSharedMemorySize, SMEM_DYN);

    init_kernel<<<NROWS / 256, 256>>>();
    {
        int warps = CB + FB + NROWS + 2 * D;
        prep_split<<<(warps * 32 + 255) / 256, 256>>>(z, ce, fe, w_c2f, w_f2c);
    }
    // coarse VQ
    vq_gemm<<<dim3(NROWS / BM, CB / BN), 256, SMEM_DYN>>>(zc_h, ce_h, nsq_c, xnsq_c, b1c, b2c, tmin);
    flag_kernel<<<NROWS / 256, 256>>>(b1c, b2c, list, cnt_c);
    exact_kernel<<<2048, 256>>>(z, 1024, ce, CB / BN, nsq_c, xnsq_c, list, cnt_c, b1c, tmin, ex);
    gather_loss<<<NROWS, 256>>>(ce, b1c, b2c, ex, z, 1024, qc, q_h, q_l);
    // MLP c2f (3-pass: res precision is argmin-critical downstream)
    mlp_gemm<3><<<dim3(NROWS / BM, D / BN), 256, SMEM_DYN>>>(q_h, q_l, w1_h, w1_l, b_c2f, h);
    ln_kernel<0><<<NROWS, 512>>>(h, g_c2f, be_c2f, z, gc_raw, gf_raw, nullptr);
    // fine VQ
    vq_gemm<<<dim3(NROWS / BM, FB / BN), 256, SMEM_DYN>>>(res_h, fe_h, nsq_f, xnsq_f, b1f, b2f, tmin);
    flag_kernel<<<NROWS / 256, 256>>>(b1f, b2f, list, cnt_f);
    exact_kernel<<<2048, 256>>>(res, D, fe, FB / BN, nsq_f, xnsq_f, list, cnt_f, b1f, tmin, ex);
    gather_loss<<<NROWS, 256>>>(fe, b1f, b2f, ex, res, D, qf, q_h, nullptr);
    // MLP f2c (1-pass: output contribution scaled by 0.1*gf)
    mlp_gemm<1><<<dim3(NROWS / BM, D / BN), 256, SMEM_DYN>>>(q_h, nullptr, w2_h, nullptr, b_f2c, h);
    ln_kernel<1><<<NROWS, 512>>>(h, g_f2c, be_f2c, z, gc_raw, gf_raw, out);
}